// round 3
// baseline (speedup 1.0000x reference)
#include <cuda_runtime.h>
#include <cuda_bf16.h>
#include <cstdint>

// Problem constants
constexpr int NN = 50000;    // nodes
constexpr int NE = 800000;   // edges
constexpr int NG = 1024;     // graphs
constexpr int H  = 128;      // hidden / node feature dim
constexpr int DS = 768;      // smiles dim
constexpr int NC = 12;       // classes

// Scratch (device globals; no allocation allowed)
__device__ float g_bufA[(size_t)NN * H];   // h_scaled (gather source)
__device__ float g_bufB[(size_t)NN * H];   // agg layer 1
__device__ float g_bufC[(size_t)NN * H];   // agg layer 2
__device__ float g_dinv[NN];
__device__ int   g_deg[NN];
__device__ float g_gsum[NG * H];
__device__ int   g_cnt[NG];

// ---------------------------------------------------------------------------
// Packed fp32x2 helpers (Blackwell dual-FMA, PTX-only)
// ---------------------------------------------------------------------------
__device__ __forceinline__ uint64_t pack2(float a, float b) {
    uint64_t r; asm("mov.b64 %0, {%1, %2};" : "=l"(r) : "f"(a), "f"(b)); return r;
}
__device__ __forceinline__ void unpack2(uint64_t v, float& a, float& b) {
    asm("mov.b64 {%0, %1}, %2;" : "=f"(a), "=f"(b) : "l"(v));
}
__device__ __forceinline__ void ffma2(uint64_t& d, uint64_t a, uint64_t b) {
    asm("fma.rn.f32x2 %0, %1, %2, %0;" : "+l"(d) : "l"(a), "l"(b));
}

// Vectorized no-return atomic add (sm_90+)
__device__ __forceinline__ void red_add_v4(float* p, float4 v) {
    asm volatile("red.global.add.v4.f32 [%0], {%1, %2, %3, %4};"
                 :: "l"(p), "f"(v.x), "f"(v.y), "f"(v.z), "f"(v.w)
                 : "memory");
}

// ---------------------------------------------------------------------------
// K0: init counters
// ---------------------------------------------------------------------------
__global__ void prep_zero_kernel(int* __restrict__ deg, int* __restrict__ cnt,
                                 float* __restrict__ gsum) {
    int i = blockIdx.x * blockDim.x + threadIdx.x;
    if (i < NN) deg[i] = 1;            // self-loop contributes 1 to degree
    if (i < NG) cnt[i] = 0;
    if (i < NG * H) gsum[i] = 0.0f;
}

// ---------------------------------------------------------------------------
// K1: degree count over edges (dst) + node counts per graph.
// ---------------------------------------------------------------------------
__global__ void count_kernel(const int* __restrict__ dst, const int* __restrict__ batch,
                             int* __restrict__ deg, int* __restrict__ cnt) {
    int i = blockIdx.x * blockDim.x + threadIdx.x;
    if (i < NE) atomicAdd(&deg[dst[i]], 1);
    if (i < NN) atomicAdd(&cnt[batch[i]], 1);
}

// ---------------------------------------------------------------------------
// K2: dinv = rsqrt(deg)
// ---------------------------------------------------------------------------
__global__ void dinv_kernel(const int* __restrict__ deg, float* __restrict__ dinv) {
    int i = blockIdx.x * blockDim.x + threadIdx.x;
    if (i < NN) dinv[i] = rsqrtf((float)deg[i]);
}

// ---------------------------------------------------------------------------
// GEMM: Out[M,128] = T(A)[M,128] @ W[128,128], then epilogue scales by
// dinv[row] and writes the result to BOTH outH (gather src) and outAgg
// (agg init = self-loop contribution, since dinv[d]*hs[d] = h[d]*dinv[d]^2).
//   mode 0: T(a) = a            (layer-1 input = raw x)
//   mode 1: T(a) = relu(biasIn[k] + dinv[row]*a)  (layer-2 input from agg1)
//
// 256 threads, block tile 128x128, per-thread 8 rows x 8 cols, W fully
// smem-resident, packed f32x2 FMAs.
// ---------------------------------------------------------------------------
constexpr int GEMM_SMEM = 65536 + 128 * 65 * 4;  // W(64KB) + Xs[128][65]

__global__ __launch_bounds__(256, 2)
void gemm_fused_kernel(const float* __restrict__ A, const float* __restrict__ W,
                       const float* __restrict__ dinv, const float* __restrict__ biasIn,
                       float* __restrict__ outH, float* __restrict__ outAgg,
                       int M, int mode)
{
    extern __shared__ char smem_raw[];
    float4* Ws = (float4*)smem_raw;                    // [128][32] float4 = W[k][c]
    float*  Xs = (float*)(smem_raw + 65536);           // [128][65]

    const int tid = threadIdx.x;
    const int tx  = tid & 15;            // col group: cols tx*8 .. tx*8+7
    const int ty  = tid >> 4;            // row base: rows ty + 16*mi
    const int row0 = blockIdx.x * 128;

    // Load W fully (once): 4096 float4s, 16 per thread.
#pragma unroll
    for (int i = 0; i < 16; i++) {
        int li = tid + i * 256;
        Ws[li] = __ldg((const float4*)W + li);
    }

    uint64_t acc[8][4];
#pragma unroll
    for (int mi = 0; mi < 8; mi++)
#pragma unroll
        for (int p = 0; p < 4; p++) acc[mi][p] = 0ull;

    for (int k0 = 0; k0 < 128; k0 += 64) {
        __syncthreads();   // also publishes Ws on first iteration
        // Load X chunk: 128 rows x 64 k = 2048 float4s, 8 per thread.
#pragma unroll
        for (int i = 0; i < 8; i++) {
            int li = tid + i * 256;
            int r  = li >> 4;            // 0..127
            int c4 = li & 15;            // 0..15 (float4 within 64-k chunk)
            int gr = row0 + r;
            float4 v = make_float4(0.f, 0.f, 0.f, 0.f);
            if (gr < M) {
                v = __ldg((const float4*)(A + (size_t)gr * 128 + k0) + c4);
                if (mode) {
                    float di = dinv[gr];
                    float4 bb = __ldg((const float4*)(biasIn + k0) + c4);
                    v.x = fmaxf(bb.x + di * v.x, 0.f);
                    v.y = fmaxf(bb.y + di * v.y, 0.f);
                    v.z = fmaxf(bb.z + di * v.z, 0.f);
                    v.w = fmaxf(bb.w + di * v.w, 0.f);
                }
            }
            float* xr = Xs + (size_t)r * 65 + c4 * 4;
            xr[0] = v.x; xr[1] = v.y; xr[2] = v.z; xr[3] = v.w;
        }
        __syncthreads();

#pragma unroll 8
        for (int kk = 0; kk < 64; kk++) {
            const ulonglong2* wp = (const ulonglong2*)&Ws[(size_t)(k0 + kk) * 32 + tx * 2];
            ulonglong2 w01 = wp[0];          // cols (0,1),(2,3) of this thread's 8
            ulonglong2 w23 = wp[1];          // cols (4,5),(6,7)
#pragma unroll
            for (int mi = 0; mi < 8; mi++) {
                float xv = Xs[(size_t)(ty + 16 * mi) * 65 + kk];
                uint64_t xx = pack2(xv, xv);
                ffma2(acc[mi][0], xx, w01.x);
                ffma2(acc[mi][1], xx, w01.y);
                ffma2(acc[mi][2], xx, w23.x);
                ffma2(acc[mi][3], xx, w23.y);
            }
        }
    }

    // Epilogue: scale by dinv[row], dual write.
#pragma unroll
    for (int mi = 0; mi < 8; mi++) {
        int row = row0 + ty + 16 * mi;
        if (row < M) {
            float d = dinv[row];
            float o[8];
#pragma unroll
            for (int p = 0; p < 4; p++) unpack2(acc[mi][p], o[2 * p], o[2 * p + 1]);
#pragma unroll
            for (int n = 0; n < 8; n++) o[n] *= d;
            float4 lo = make_float4(o[0], o[1], o[2], o[3]);
            float4 hi = make_float4(o[4], o[5], o[6], o[7]);
            size_t base = (size_t)row * 128 + tx * 8;
            *(float4*)(outH + base)       = lo;
            *(float4*)(outH + base + 4)   = hi;
            *(float4*)(outAgg + base)     = lo;
            *(float4*)(outAgg + base + 4) = hi;
        }
    }
}

// ---------------------------------------------------------------------------
// Edge aggregation: agg[dst,:] += h_scaled[src,:]. One warp per edge.
// ---------------------------------------------------------------------------
__global__ __launch_bounds__(256)
void edge_kernel(const int* __restrict__ src, const int* __restrict__ dst,
                 const float* __restrict__ hs, float* __restrict__ agg) {
    int g = blockIdx.x * blockDim.x + threadIdx.x;
    int e = g >> 5;
    if (e >= NE) return;
    int lane = g & 31;
    int s = __ldg(&src[e]);
    int d = __ldg(&dst[e]);
    float4 v = __ldg((const float4*)(hs + (size_t)s * 128) + lane);
    red_add_v4(agg + (size_t)d * 128 + (size_t)lane * 4, v);
}

// ---------------------------------------------------------------------------
// Pooling: gsum[batch[i],:] += relu(bg2 + dinv[i]*agg2[i,:]). One warp/node.
// ---------------------------------------------------------------------------
__global__ __launch_bounds__(256)
void pool_kernel(const float* __restrict__ agg, const float* __restrict__ dinv,
                 const float* __restrict__ bias, const int* __restrict__ batch,
                 float* __restrict__ gsum) {
    int g = blockIdx.x * blockDim.x + threadIdx.x;
    int node = g >> 5;
    if (node >= NN) return;
    int lane = g & 31;
    int b = __ldg(&batch[node]);
    float di = __ldg(&dinv[node]);
    float4 v  = __ldg((const float4*)(agg + (size_t)node * 128) + lane);
    float4 bb = __ldg((const float4*)bias + lane);
    v.x = fmaxf(bb.x + di * v.x, 0.f);
    v.y = fmaxf(bb.y + di * v.y, 0.f);
    v.z = fmaxf(bb.z + di * v.z, 0.f);
    v.w = fmaxf(bb.w + di * v.w, 0.f);
    red_add_v4(gsum + (size_t)b * 128 + (size_t)lane * 4, v);
}

// ---------------------------------------------------------------------------
// Fused head: 8 graphs per block, 128 threads (thread j owns output col j).
//   s = relu(smiles@Ws1+bs1)@Ws2+bs2 ; g = gsum/cnt ; f = relu([s,g]@Wf+bf)
//   out = f@Wo+bo
// ---------------------------------------------------------------------------
__global__ __launch_bounds__(128)
void final_kernel(const float* __restrict__ smiles,
                  const float* __restrict__ Ws1, const float* __restrict__ bs1,
                  const float* __restrict__ Ws2, const float* __restrict__ bs2,
                  const float* __restrict__ Wf,  const float* __restrict__ bf,
                  const float* __restrict__ Wo,  const float* __restrict__ bo,
                  const float* __restrict__ gsum, const int* __restrict__ cnt,
                  float* __restrict__ out) {
    __shared__ float sm[8][DS];        // 24KB
    __shared__ float s1[8][H];
    __shared__ float comb[8][2 * H];
    __shared__ float fz[8][H];

    const int b0 = blockIdx.x * 8;
    const int j = threadIdx.x;

    // cooperative smiles load: 8*768 floats = 1536 float4s
    const float4* sp = (const float4*)(smiles + (size_t)b0 * DS);
#pragma unroll
    for (int i = 0; i < 12; i++)
        ((float4*)sm)[j + i * 128] = __ldg(sp + j + i * 128);
    __syncthreads();

    float a[8];
#pragma unroll
    for (int g = 0; g < 8; g++) a[g] = 0.f;
#pragma unroll 4
    for (int k = 0; k < DS; k++) {
        float w = __ldg(&Ws1[(size_t)k * H + j]);
#pragma unroll
        for (int g = 0; g < 8; g++) a[g] += sm[g][k] * w;
    }
    {
        float b1 = __ldg(&bs1[j]);
#pragma unroll
        for (int g = 0; g < 8; g++) s1[g][j] = fmaxf(a[g] + b1, 0.f);
    }
    __syncthreads();

#pragma unroll
    for (int g = 0; g < 8; g++) a[g] = 0.f;
#pragma unroll 4
    for (int k = 0; k < H; k++) {
        float w = __ldg(&Ws2[(size_t)k * H + j]);
#pragma unroll
        for (int g = 0; g < 8; g++) a[g] += s1[g][k] * w;
    }
    {
        float b2 = __ldg(&bs2[j]);
#pragma unroll
        for (int g = 0; g < 8; g++) {
            comb[g][j] = a[g] + b2;
            float c = (float)__ldg(&cnt[b0 + g]);
            comb[g][H + j] = __ldg(&gsum[(size_t)(b0 + g) * H + j]) / fmaxf(c, 1.f);
        }
    }
    __syncthreads();

#pragma unroll
    for (int g = 0; g < 8; g++) a[g] = 0.f;
#pragma unroll 4
    for (int k = 0; k < 2 * H; k++) {
        float w = __ldg(&Wf[(size_t)k * H + j]);
#pragma unroll
        for (int g = 0; g < 8; g++) a[g] += comb[g][k] * w;
    }
    {
        float bfv = __ldg(&bf[j]);
#pragma unroll
        for (int g = 0; g < 8; g++) fz[g][j] = fmaxf(a[g] + bfv, 0.f);
    }
    __syncthreads();

    if (j < 8 * NC) {
        int g = j / NC, c = j % NC;
        float s = __ldg(&bo[c]);
        for (int k = 0; k < H; k++)
            s += fz[g][k] * __ldg(&Wo[(size_t)k * NC + c]);
        out[(size_t)(b0 + g) * NC + c] = s;
    }
}

// ---------------------------------------------------------------------------
extern "C" void kernel_launch(void* const* d_in, const int* in_sizes, int n_in,
                              void* d_out, int out_size) {
    const float* smiles = (const float*)d_in[0];
    const float* x      = (const float*)d_in[1];
    const int*   ei     = (const int*)d_in[2];
    const int*   batch  = (const int*)d_in[3];
    const float* Ws1 = (const float*)d_in[4];
    const float* bs1 = (const float*)d_in[5];
    const float* Ws2 = (const float*)d_in[6];
    const float* bs2 = (const float*)d_in[7];
    const float* Wg1 = (const float*)d_in[8];
    const float* bg1 = (const float*)d_in[9];
    const float* Wg2 = (const float*)d_in[10];
    const float* bg2 = (const float*)d_in[11];
    const float* Wf  = (const float*)d_in[12];
    const float* bf  = (const float*)d_in[13];
    const float* Wo  = (const float*)d_in[14];
    const float* bo  = (const float*)d_in[15];
    float* out = (float*)d_out;

    float *bufA, *bufB, *bufC, *dinv, *gsum;
    int *deg, *cnt;
    cudaGetSymbolAddress((void**)&bufA, g_bufA);
    cudaGetSymbolAddress((void**)&bufB, g_bufB);
    cudaGetSymbolAddress((void**)&bufC, g_bufC);
    cudaGetSymbolAddress((void**)&dinv, g_dinv);
    cudaGetSymbolAddress((void**)&deg,  g_deg);
    cudaGetSymbolAddress((void**)&gsum, g_gsum);
    cudaGetSymbolAddress((void**)&cnt,  g_cnt);

    // Idempotent, not a stream op — safe during graph capture; no static guard.
    cudaFuncSetAttribute(gemm_fused_kernel,
                         cudaFuncAttributeMaxDynamicSharedMemorySize, GEMM_SMEM);

    const int* src = ei;
    const int* dst = ei + NE;

    const int T = 256;
    prep_zero_kernel<<<(NG * H + T - 1) / T, T>>>(deg, cnt, gsum);
    count_kernel<<<(NE + T - 1) / T, T>>>(dst, batch, deg, cnt);
    dinv_kernel<<<(NN + T - 1) / T, T>>>(deg, dinv);

    const int GB = (NN + 127) / 128;   // gemm blocks

    // --- GCN layer 1: h_scaled -> bufA (gather) and bufB (agg init) ---
    gemm_fused_kernel<<<GB, 256, GEMM_SMEM>>>(x, Wg1, dinv, bg1, bufA, bufB, NN, 0);
    edge_kernel<<<(NE * 32 + T - 1) / T, T>>>(src, dst, bufA, bufB);

    // --- GCN layer 2: reads agg1 (bufB) with relu(bg1 + dinv*·) transform ---
    gemm_fused_kernel<<<GB, 256, GEMM_SMEM>>>(bufB, Wg2, dinv, bg1, bufA, bufC, NN, 1);
    edge_kernel<<<(NE * 32 + T - 1) / T, T>>>(src, dst, bufA, bufC);

    // --- mean pool: relu(bg2 + dinv*agg2) summed per graph ---
    pool_kernel<<<(NN * 32 + T - 1) / T, T>>>(bufC, dinv, bg2, batch, gsum);

    // --- SMILES MLP + fusion + output head ---
    final_kernel<<<NG / 8, 128>>>(smiles, Ws1, bs1, Ws2, bs2, Wf, bf, Wo, bo,
                                  gsum, cnt, out);
}

// round 5
// speedup vs baseline: 1.3841x; 1.3841x over previous
#include <cuda_runtime.h>
#include <cuda_bf16.h>
#include <cstdint>

// Problem constants
constexpr int NN = 50000;    // nodes
constexpr int NE = 800000;   // edges
constexpr int NG = 1024;     // graphs
constexpr int H  = 128;      // hidden / node feature dim
constexpr int DS = 768;      // smiles dim
constexpr int NC = 12;       // classes

constexpr int SCAN_B  = 256;
constexpr int SCAN_NB = (NN + SCAN_B - 1) / SCAN_B;   // 196

// Scratch (device globals; no allocation allowed)
__device__ float g_bufA[(size_t)NN * H];   // hs (gather source, both layers)
__device__ float g_bufB[(size_t)NN * H];   // layer-1 aggregate sum
__device__ float g_dinv[NN];
__device__ int   g_edeg[NN];               // edge-only in-degree
__device__ int   g_off[NN + 1];            // CSR offsets (by dst)
__device__ int   g_cursor[NN];
__device__ int   g_csr[NE];                // src ids grouped by dst
__device__ int   g_blocksum[SCAN_B];
__device__ int   g_blockoff[SCAN_B];
__device__ float g_gsum[NG * H];
__device__ int   g_cnt[NG];

// ---------------------------------------------------------------------------
// Packed fp32x2 helpers (Blackwell dual-FMA, PTX-only)
// ---------------------------------------------------------------------------
__device__ __forceinline__ uint64_t pack2(float a, float b) {
    uint64_t r; asm("mov.b64 %0, {%1, %2};" : "=l"(r) : "f"(a), "f"(b)); return r;
}
__device__ __forceinline__ void unpack2(uint64_t v, float& a, float& b) {
    asm("mov.b64 {%0, %1}, %2;" : "=f"(a), "=f"(b) : "l"(v));
}
__device__ __forceinline__ void ffma2(uint64_t& d, uint64_t a, uint64_t b) {
    asm("fma.rn.f32x2 %0, %1, %2, %0;" : "+l"(d) : "l"(a), "l"(b));
}
__device__ __forceinline__ void red_add_v4(float* p, float4 v) {
    asm volatile("red.global.add.v4.f32 [%0], {%1, %2, %3, %4};"
                 :: "l"(p), "f"(v.x), "f"(v.y), "f"(v.z), "f"(v.w)
                 : "memory");
}

// ---------------------------------------------------------------------------
// K0: zero/init
// ---------------------------------------------------------------------------
__global__ void prep_zero_kernel(int* __restrict__ edeg, int* __restrict__ cnt,
                                 float* __restrict__ gsum, int* __restrict__ off) {
    int i = blockIdx.x * blockDim.x + threadIdx.x;
    if (i < NN) edeg[i] = 0;
    if (i < NG) cnt[i] = 0;
    if (i < NG * H) gsum[i] = 0.0f;
    if (i == 0) off[NN] = NE;
}

// ---------------------------------------------------------------------------
// K1: in-degree (edges only) + node counts per graph
// ---------------------------------------------------------------------------
__global__ void count_kernel(const int* __restrict__ dst, const int* __restrict__ batch,
                             int* __restrict__ edeg, int* __restrict__ cnt) {
    int i = blockIdx.x * blockDim.x + threadIdx.x;
    if (i < NE) atomicAdd(&edeg[dst[i]], 1);
    if (i < NN) atomicAdd(&cnt[batch[i]], 1);
}

// ---------------------------------------------------------------------------
// K2: dinv = rsqrt(edeg + 1)   (+1 = self loop)
// ---------------------------------------------------------------------------
__global__ void dinv_kernel(const int* __restrict__ edeg, float* __restrict__ dinv) {
    int i = blockIdx.x * blockDim.x + threadIdx.x;
    if (i < NN) dinv[i] = rsqrtf((float)(edeg[i] + 1));
}

// ---------------------------------------------------------------------------
// Scan stage 1: per-block sums of edeg
// ---------------------------------------------------------------------------
__global__ __launch_bounds__(SCAN_B)
void scan1_kernel(const int* __restrict__ edeg, int* __restrict__ blocksum) {
    __shared__ int sh[SCAN_B];
    int t = threadIdx.x;
    int i = blockIdx.x * SCAN_B + t;
    sh[t] = (i < NN) ? edeg[i] : 0;
    __syncthreads();
    for (int d = SCAN_B / 2; d > 0; d >>= 1) {
        if (t < d) sh[t] += sh[t + d];
        __syncthreads();
    }
    if (t == 0) blocksum[blockIdx.x] = sh[0];
}

// ---------------------------------------------------------------------------
// Scan stage 2: single-block exclusive scan of block sums
// ---------------------------------------------------------------------------
__global__ __launch_bounds__(SCAN_B)
void scan2_kernel(const int* __restrict__ blocksum, int* __restrict__ blockoff) {
    __shared__ int sh[SCAN_B];
    int t = threadIdx.x;
    int v = (t < SCAN_NB) ? blocksum[t] : 0;
    sh[t] = v;
    __syncthreads();
    for (int d = 1; d < SCAN_B; d <<= 1) {
        int add = (t >= d) ? sh[t - d] : 0;
        __syncthreads();
        sh[t] += add;
        __syncthreads();
    }
    blockoff[t] = sh[t] - v;   // exclusive
}

// ---------------------------------------------------------------------------
// Scan stage 3: per-element exclusive offsets; init cursor
// ---------------------------------------------------------------------------
__global__ __launch_bounds__(SCAN_B)
void scan3_kernel(const int* __restrict__ edeg, const int* __restrict__ blockoff,
                  int* __restrict__ off, int* __restrict__ cursor) {
    __shared__ int wsum[8], wbase[8];
    int t = threadIdx.x;
    int lane = t & 31, wid = t >> 5;
    int i = blockIdx.x * SCAN_B + t;
    int v = (i < NN) ? edeg[i] : 0;
    // inclusive warp scan
    int x = v;
#pragma unroll
    for (int d = 1; d < 32; d <<= 1) {
        int y = __shfl_up_sync(0xffffffff, x, d);
        if (lane >= d) x += y;
    }
    if (lane == 31) wsum[wid] = x;
    __syncthreads();
    if (t == 0) {
        int run = 0;
#pragma unroll
        for (int k = 0; k < 8; k++) { wbase[k] = run; run += wsum[k]; }
    }
    __syncthreads();
    if (i < NN) {
        int e = blockoff[blockIdx.x] + wbase[wid] + (x - v);
        off[i] = e;
        cursor[i] = e;
    }
}

// ---------------------------------------------------------------------------
// K3: scatter edges into CSR (grouped by dst)
// ---------------------------------------------------------------------------
__global__ void scatter_kernel(const int* __restrict__ src, const int* __restrict__ dst,
                               int* __restrict__ cursor, int* __restrict__ csr) {
    int i = blockIdx.x * blockDim.x + threadIdx.x;
    if (i >= NE) return;
    int d = dst[i];
    int p = atomicAdd(&cursor[d], 1);
    csr[p] = src[i];
}

// ---------------------------------------------------------------------------
// Persistent GEMM: hs[M,128] = dinv[row] * (T(A)[M,128] @ W[128,128])
//   mode 0: T(a) = a
//   mode 1: T(a) = relu(biasIn[k] + dinv[row]*a)
// W fully smem-resident (loaded once per block), X in 32-k chunks.
// ---------------------------------------------------------------------------
constexpr int GEMM_SMEM = 65536 + 128 * 33 * 4;   // W + Xs[128][33]
constexpr int GEMM_TILES = (NN + 127) / 128;      // 391

__global__ __launch_bounds__(256, 2)
void gemm_fused_kernel(const float* __restrict__ A, const float* __restrict__ W,
                       const float* __restrict__ dinv, const float* __restrict__ biasIn,
                       float* __restrict__ outH, int M, int mode)
{
    extern __shared__ char smem_raw[];
    float4* Ws = (float4*)smem_raw;                 // [128][32] float4 = W[k][c]
    float*  Xs = (float*)(smem_raw + 65536);        // [128][33]

    const int tid = threadIdx.x;
    const int tx  = tid & 15;          // col group: cols tx*8 .. tx*8+7
    const int ty  = tid >> 4;          // row base: rows ty + 16*mi

    // Load W once (4096 float4s, 16/thread); published by first chunk sync.
#pragma unroll
    for (int i = 0; i < 16; i++)
        Ws[tid + i * 256] = __ldg((const float4*)W + tid + i * 256);

    for (int tile = blockIdx.x; tile < GEMM_TILES; tile += gridDim.x) {
        const int row0 = tile * 128;

        uint64_t acc[8][4];
#pragma unroll
        for (int mi = 0; mi < 8; mi++)
#pragma unroll
            for (int p = 0; p < 4; p++) acc[mi][p] = 0ull;

        for (int k0 = 0; k0 < 128; k0 += 32) {
            __syncthreads();   // protects Xs from prior compute / publishes W
            // Stage X chunk: 128 rows x 32 k = 1024 float4s, 4/thread.
#pragma unroll
            for (int i = 0; i < 4; i++) {
                int li = tid + i * 256;
                int r  = li >> 3;          // 0..127
                int c4 = li & 7;           // 0..7
                int gr = row0 + r;
                float4 v = make_float4(0.f, 0.f, 0.f, 0.f);
                if (gr < M) {
                    v = __ldg((const float4*)(A + (size_t)gr * 128 + k0) + c4);
                    if (mode) {
                        float di = __ldg(&dinv[gr]);
                        float4 bb = __ldg((const float4*)(biasIn + k0) + c4);
                        v.x = fmaxf(bb.x + di * v.x, 0.f);
                        v.y = fmaxf(bb.y + di * v.y, 0.f);
                        v.z = fmaxf(bb.z + di * v.z, 0.f);
                        v.w = fmaxf(bb.w + di * v.w, 0.f);
                    }
                }
                float* xr = Xs + r * 33 + c4 * 4;
                xr[0] = v.x; xr[1] = v.y; xr[2] = v.z; xr[3] = v.w;
            }
            __syncthreads();

#pragma unroll
            for (int kk = 0; kk < 32; kk++) {
                const ulonglong2* wp =
                    (const ulonglong2*)&Ws[(size_t)(k0 + kk) * 32 + tx * 2];
                ulonglong2 w01 = wp[0];
                ulonglong2 w23 = wp[1];
#pragma unroll
                for (int mi = 0; mi < 8; mi++) {
                    float xv = Xs[(ty + 16 * mi) * 33 + kk];
                    uint64_t xx = pack2(xv, xv);
                    ffma2(acc[mi][0], xx, w01.x);
                    ffma2(acc[mi][1], xx, w01.y);
                    ffma2(acc[mi][2], xx, w23.x);
                    ffma2(acc[mi][3], xx, w23.y);
                }
            }
        }

        // Epilogue: scale by dinv[row], single write.
#pragma unroll
        for (int mi = 0; mi < 8; mi++) {
            int row = row0 + ty + 16 * mi;
            if (row < M) {
                float d = __ldg(&dinv[row]);
                float o[8];
#pragma unroll
                for (int p = 0; p < 4; p++) unpack2(acc[mi][p], o[2 * p], o[2 * p + 1]);
#pragma unroll
                for (int n = 0; n < 8; n++) o[n] *= d;
                size_t base = (size_t)row * 128 + tx * 8;
                *(float4*)(outH + base)     = make_float4(o[0], o[1], o[2], o[3]);
                *(float4*)(outH + base + 4) = make_float4(o[4], o[5], o[6], o[7]);
            }
        }
    }
}

// ---------------------------------------------------------------------------
// Aggregate: one warp per node. sum = hs[n] + sum_{src in CSR[n]} hs[src].
//   mode 0: write raw sum to outSum
//   mode 1: v = relu(bg2 + dinv[n]*sum); red_add to gsum[batch[n]]  (fused pool)
// ---------------------------------------------------------------------------
__global__ __launch_bounds__(256)
void agg_kernel(const float4* __restrict__ hsv, const int* __restrict__ off,
                const int* __restrict__ csr, const float* __restrict__ dinv,
                const float* __restrict__ bias, const int* __restrict__ batch,
                float4* __restrict__ outSum, float* __restrict__ gsum, int mode)
{
    int w = (blockIdx.x * blockDim.x + threadIdx.x) >> 5;
    if (w >= NN) return;
    int lane = threadIdx.x & 31;
    int o0 = __ldg(&off[w]);
    int o1 = __ldg(&off[w + 1]);

    float4 acc = __ldg(&hsv[(size_t)w * 32 + lane]);   // self-loop term

    for (int j = o0; j < o1; j += 32) {
        int s = (j + lane < o1) ? __ldg(&csr[j + lane]) : 0;
        int n = min(32, o1 - j);
        for (int t = 0; t < n; t++) {
            int si = __shfl_sync(0xffffffff, s, t);
            float4 v = __ldg(&hsv[(size_t)si * 32 + lane]);
            acc.x += v.x; acc.y += v.y; acc.z += v.z; acc.w += v.w;
        }
    }

    if (mode == 0) {
        outSum[(size_t)w * 32 + lane] = acc;
    } else {
        float di = __ldg(&dinv[w]);
        float4 bb = __ldg((const float4*)bias + lane);
        acc.x = fmaxf(bb.x + di * acc.x, 0.f);
        acc.y = fmaxf(bb.y + di * acc.y, 0.f);
        acc.z = fmaxf(bb.z + di * acc.z, 0.f);
        acc.w = fmaxf(bb.w + di * acc.w, 0.f);
        int b = __ldg(&batch[w]);
        red_add_v4(gsum + (size_t)b * 128 + lane * 4, acc);
    }
}

// ---------------------------------------------------------------------------
// Fused head: 8 graphs per block, 128 threads (thread j owns output col j).
// ---------------------------------------------------------------------------
__global__ __launch_bounds__(128)
void final_kernel(const float* __restrict__ smiles,
                  const float* __restrict__ Ws1, const float* __restrict__ bs1,
                  const float* __restrict__ Ws2, const float* __restrict__ bs2,
                  const float* __restrict__ Wf,  const float* __restrict__ bf,
                  const float* __restrict__ Wo,  const float* __restrict__ bo,
                  const float* __restrict__ gsum, const int* __restrict__ cnt,
                  float* __restrict__ out) {
    __shared__ float sm[8][DS];
    __shared__ float s1[8][H];
    __shared__ float comb[8][2 * H];
    __shared__ float fz[8][H];

    const int b0 = blockIdx.x * 8;
    const int j = threadIdx.x;

    const float4* sp = (const float4*)(smiles + (size_t)b0 * DS);
#pragma unroll
    for (int i = 0; i < 12; i++)
        ((float4*)sm)[j + i * 128] = __ldg(sp + j + i * 128);
    __syncthreads();

    float a[8];
#pragma unroll
    for (int g = 0; g < 8; g++) a[g] = 0.f;
#pragma unroll 4
    for (int k = 0; k < DS; k++) {
        float w = __ldg(&Ws1[(size_t)k * H + j]);
#pragma unroll
        for (int g = 0; g < 8; g++) a[g] += sm[g][k] * w;
    }
    {
        float b1 = __ldg(&bs1[j]);
#pragma unroll
        for (int g = 0; g < 8; g++) s1[g][j] = fmaxf(a[g] + b1, 0.f);
    }
    __syncthreads();

#pragma unroll
    for (int g = 0; g < 8; g++) a[g] = 0.f;
#pragma unroll 4
    for (int k = 0; k < H; k++) {
        float w = __ldg(&Ws2[(size_t)k * H + j]);
#pragma unroll
        for (int g = 0; g < 8; g++) a[g] += s1[g][k] * w;
    }
    {
        float b2 = __ldg(&bs2[j]);
#pragma unroll
        for (int g = 0; g < 8; g++) {
            comb[g][j] = a[g] + b2;
            float c = (float)__ldg(&cnt[b0 + g]);
            comb[g][H + j] = __ldg(&gsum[(size_t)(b0 + g) * H + j]) / fmaxf(c, 1.f);
        }
    }
    __syncthreads();

#pragma unroll
    for (int g = 0; g < 8; g++) a[g] = 0.f;
#pragma unroll 4
    for (int k = 0; k < 2 * H; k++) {
        float w = __ldg(&Wf[(size_t)k * H + j]);
#pragma unroll
        for (int g = 0; g < 8; g++) a[g] += comb[g][k] * w;
    }
    {
        float bfv = __ldg(&bf[j]);
#pragma unroll
        for (int g = 0; g < 8; g++) fz[g][j] = fmaxf(a[g] + bfv, 0.f);
    }
    __syncthreads();

    if (j < 8 * NC) {
        int g = j / NC, c = j % NC;
        float s = __ldg(&bo[c]);
        for (int k = 0; k < H; k++)
            s += fz[g][k] * __ldg(&Wo[(size_t)k * NC + c]);
        out[(size_t)(b0 + g) * NC + c] = s;
    }
}

// ---------------------------------------------------------------------------
extern "C" void kernel_launch(void* const* d_in, const int* in_sizes, int n_in,
                              void* d_out, int out_size) {
    const float* smiles = (const float*)d_in[0];
    const float* x      = (const float*)d_in[1];
    const int*   ei     = (const int*)d_in[2];
    const int*   batch  = (const int*)d_in[3];
    const float* Ws1 = (const float*)d_in[4];
    const float* bs1 = (const float*)d_in[5];
    const float* Ws2 = (const float*)d_in[6];
    const float* bs2 = (const float*)d_in[7];
    const float* Wg1 = (const float*)d_in[8];
    const float* bg1 = (const float*)d_in[9];
    const float* Wg2 = (const float*)d_in[10];
    const float* bg2 = (const float*)d_in[11];
    const float* Wf  = (const float*)d_in[12];
    const float* bf  = (const float*)d_in[13];
    const float* Wo  = (const float*)d_in[14];
    const float* bo  = (const float*)d_in[15];
    float* out = (float*)d_out;

    float *bufA, *bufB, *dinv, *gsum;
    int *edeg, *off, *cursor, *csr, *blocksum, *blockoff, *cnt;
    cudaGetSymbolAddress((void**)&bufA, g_bufA);
    cudaGetSymbolAddress((void**)&bufB, g_bufB);
    cudaGetSymbolAddress((void**)&dinv, g_dinv);
    cudaGetSymbolAddress((void**)&edeg, g_edeg);
    cudaGetSymbolAddress((void**)&off,  g_off);
    cudaGetSymbolAddress((void**)&cursor, g_cursor);
    cudaGetSymbolAddress((void**)&csr,  g_csr);
    cudaGetSymbolAddress((void**)&blocksum, g_blocksum);
    cudaGetSymbolAddress((void**)&blockoff, g_blockoff);
    cudaGetSymbolAddress((void**)&gsum, g_gsum);
    cudaGetSymbolAddress((void**)&cnt,  g_cnt);

    cudaFuncSetAttribute(gemm_fused_kernel,
                         cudaFuncAttributeMaxDynamicSharedMemorySize, GEMM_SMEM);

    const int* src = ei;
    const int* dst = ei + NE;

    const int T = 256;

    // --- preprocessing: degrees, counts, CSR by dst ---
    prep_zero_kernel<<<(NG * H + T - 1) / T, T>>>(edeg, cnt, gsum, off);
    count_kernel<<<(NE + T - 1) / T, T>>>(dst, batch, edeg, cnt);
    dinv_kernel<<<(NN + T - 1) / T, T>>>(edeg, dinv);
    scan1_kernel<<<SCAN_NB, SCAN_B>>>(edeg, blocksum);
    scan2_kernel<<<1, SCAN_B>>>(blocksum, blockoff);
    scan3_kernel<<<SCAN_NB, SCAN_B>>>(edeg, blockoff, off, cursor);
    scatter_kernel<<<(NE + T - 1) / T, T>>>(src, dst, cursor, csr);

    const int GEMM_GRID = 296;     // 2 per SM, persistent
    const int AGG_GRID  = (NN * 32 + T - 1) / T;

    // --- GCN layer 1 ---
    gemm_fused_kernel<<<GEMM_GRID, 256, GEMM_SMEM>>>(x, Wg1, dinv, bg1, bufA, NN, 0);
    agg_kernel<<<AGG_GRID, T>>>((const float4*)bufA, off, csr, dinv, bg2, batch,
                                (float4*)bufB, gsum, 0);

    // --- GCN layer 2 (input transform relu(bg1 + dinv*sum1) inside GEMM) ---
    gemm_fused_kernel<<<GEMM_GRID, 256, GEMM_SMEM>>>(bufB, Wg2, dinv, bg1, bufA, NN, 1);
    // aggregate + fused pool into gsum
    agg_kernel<<<AGG_GRID, T>>>((const float4*)bufA, off, csr, dinv, bg2, batch,
                                (float4*)bufB, gsum, 1);

    // --- SMILES MLP + fusion + output head ---
    final_kernel<<<NG / 8, 128>>>(smiles, Ws1, bs1, Ws2, bs2, Wf, bf, Wo, bo,
                                  gsum, cnt, out);
}

// round 7
// speedup vs baseline: 1.6784x; 1.2126x over previous
#include <cuda_runtime.h>
#include <cuda_bf16.h>
#include <cstdint>

// Problem constants
constexpr int NN = 50000;    // nodes
constexpr int NE = 800000;   // edges
constexpr int NG = 1024;     // graphs
constexpr int H  = 128;      // hidden / node feature dim
constexpr int DS = 768;      // smiles dim
constexpr int NC = 12;       // classes

constexpr int SCAN_B  = 256;
constexpr int SCAN_NB = (NN + SCAN_B - 1) / SCAN_B;   // 196

// Scratch (device globals; no allocation allowed)
__device__ float g_bufA[(size_t)NN * H];   // hs (gather source, both layers)
__device__ float g_bufB[(size_t)NN * H];   // layer-1 aggregate sum
__device__ float g_dinv[NN];
__device__ int   g_edeg[NN];               // edge-only in-degree
__device__ int   g_off[NN + 1];            // CSR offsets (by dst)
__device__ int   g_cursor[NN];
__device__ int   g_csr[NE];                // src ids grouped by dst
__device__ int   g_blocksum[SCAN_B];
__device__ int   g_blockoff[SCAN_B];
__device__ float g_gsum[NG * H];
__device__ int   g_cnt[NG];

// ---------------------------------------------------------------------------
// Helpers
// ---------------------------------------------------------------------------
__device__ __forceinline__ float to_tf32(float x) {
    unsigned r;  // cvt to tf32 requires a .b32 destination register
    asm("cvt.rna.tf32.f32 %0, %1;" : "=r"(r) : "f"(x));
    return __uint_as_float(r);
}
__device__ __forceinline__ void mma_tf32(float& d0, float& d1, float& d2, float& d3,
                                         float a0, float a1, float a2, float a3,
                                         float b0, float b1) {
    asm volatile(
        "mma.sync.aligned.m16n8k8.row.col.f32.tf32.tf32.f32 "
        "{%0,%1,%2,%3}, {%4,%5,%6,%7}, {%8,%9}, {%0,%1,%2,%3};"
        : "+f"(d0), "+f"(d1), "+f"(d2), "+f"(d3)
        : "r"(__float_as_uint(a0)), "r"(__float_as_uint(a1)),
          "r"(__float_as_uint(a2)), "r"(__float_as_uint(a3)),
          "r"(__float_as_uint(b0)), "r"(__float_as_uint(b1)));
}
__device__ __forceinline__ void red_add_v4(float* p, float4 v) {
    asm volatile("red.global.add.v4.f32 [%0], {%1, %2, %3, %4};"
                 :: "l"(p), "f"(v.x), "f"(v.y), "f"(v.z), "f"(v.w)
                 : "memory");
}

// ---------------------------------------------------------------------------
// K0: zero/init
// ---------------------------------------------------------------------------
__global__ void prep_zero_kernel(int* __restrict__ edeg, int* __restrict__ cnt,
                                 float* __restrict__ gsum, int* __restrict__ off) {
    int i = blockIdx.x * blockDim.x + threadIdx.x;
    if (i < NN) edeg[i] = 0;
    if (i < NG) cnt[i] = 0;
    if (i < NG * H) gsum[i] = 0.0f;
    if (i == 0) off[NN] = NE;
}

// ---------------------------------------------------------------------------
// K1: in-degree (edges only) + node counts per graph
// ---------------------------------------------------------------------------
__global__ void count_kernel(const int* __restrict__ dst, const int* __restrict__ batch,
                             int* __restrict__ edeg, int* __restrict__ cnt) {
    int i = blockIdx.x * blockDim.x + threadIdx.x;
    if (i < NE) atomicAdd(&edeg[dst[i]], 1);
    if (i < NN) atomicAdd(&cnt[batch[i]], 1);
}

// ---------------------------------------------------------------------------
// K2: dinv = rsqrt(edeg + 1)
// ---------------------------------------------------------------------------
__global__ void dinv_kernel(const int* __restrict__ edeg, float* __restrict__ dinv) {
    int i = blockIdx.x * blockDim.x + threadIdx.x;
    if (i < NN) dinv[i] = rsqrtf((float)(edeg[i] + 1));
}

// ---------------------------------------------------------------------------
// Scan stage 1: per-block sums of edeg
// ---------------------------------------------------------------------------
__global__ __launch_bounds__(SCAN_B)
void scan1_kernel(const int* __restrict__ edeg, int* __restrict__ blocksum) {
    __shared__ int sh[SCAN_B];
    int t = threadIdx.x;
    int i = blockIdx.x * SCAN_B + t;
    sh[t] = (i < NN) ? edeg[i] : 0;
    __syncthreads();
    for (int d = SCAN_B / 2; d > 0; d >>= 1) {
        if (t < d) sh[t] += sh[t + d];
        __syncthreads();
    }
    if (t == 0) blocksum[blockIdx.x] = sh[0];
}

// ---------------------------------------------------------------------------
// Scan stage 2: single-block exclusive scan of block sums
// ---------------------------------------------------------------------------
__global__ __launch_bounds__(SCAN_B)
void scan2_kernel(const int* __restrict__ blocksum, int* __restrict__ blockoff) {
    __shared__ int sh[SCAN_B];
    int t = threadIdx.x;
    int v = (t < SCAN_NB) ? blocksum[t] : 0;
    sh[t] = v;
    __syncthreads();
    for (int d = 1; d < SCAN_B; d <<= 1) {
        int add = (t >= d) ? sh[t - d] : 0;
        __syncthreads();
        sh[t] += add;
        __syncthreads();
    }
    blockoff[t] = sh[t] - v;   // exclusive
}

// ---------------------------------------------------------------------------
// Scan stage 3: per-element exclusive offsets; init cursor
// ---------------------------------------------------------------------------
__global__ __launch_bounds__(SCAN_B)
void scan3_kernel(const int* __restrict__ edeg, const int* __restrict__ blockoff,
                  int* __restrict__ off, int* __restrict__ cursor) {
    __shared__ int wsum[8], wbase[8];
    int t = threadIdx.x;
    int lane = t & 31, wid = t >> 5;
    int i = blockIdx.x * SCAN_B + t;
    int v = (i < NN) ? edeg[i] : 0;
    int x = v;
#pragma unroll
    for (int d = 1; d < 32; d <<= 1) {
        int y = __shfl_up_sync(0xffffffff, x, d);
        if (lane >= d) x += y;
    }
    if (lane == 31) wsum[wid] = x;
    __syncthreads();
    if (t == 0) {
        int run = 0;
#pragma unroll
        for (int k = 0; k < 8; k++) { wbase[k] = run; run += wsum[k]; }
    }
    __syncthreads();
    if (i < NN) {
        int e = blockoff[blockIdx.x] + wbase[wid] + (x - v);
        off[i] = e;
        cursor[i] = e;
    }
}

// ---------------------------------------------------------------------------
// K3: scatter edges into CSR (grouped by dst)
// ---------------------------------------------------------------------------
__global__ void scatter_kernel(const int* __restrict__ src, const int* __restrict__ dst,
                               int* __restrict__ cursor, int* __restrict__ csr) {
    int i = blockIdx.x * blockDim.x + threadIdx.x;
    if (i >= NE) return;
    int d = dst[i];
    int p = atomicAdd(&cursor[d], 1);
    csr[p] = src[i];
}

// ---------------------------------------------------------------------------
// Persistent tf32 tensor-core GEMM:
//   hs[M,128] = dinv[row] * (T(A)[M,128] @ W[128,128])
//   mode 0: T(a) = a
//   mode 1: T(a) = relu(biasIn[k] + dinv[row]*a)
// Block: 256 thr (8 warps), tile 128 rows x 128 cols. Warp wi owns cols
// wi*16..wi*16+15. W tf32-resident in smem [128][136]; X staged in 64-k
// chunks [128][68] (tf32). mma.m16n8k8.
// ---------------------------------------------------------------------------
constexpr int WS_STRIDE = 136;
constexpr int XS_STRIDE = 68;
constexpr int GEMM_SMEM = 128 * WS_STRIDE * 4 + 128 * XS_STRIDE * 4;  // 104448
constexpr int GEMM_TILES = (NN + 127) / 128;      // 391

__global__ __launch_bounds__(256, 2)
void gemm_tc_kernel(const float* __restrict__ A, const float* __restrict__ W,
                    const float* __restrict__ dinv, const float* __restrict__ biasIn,
                    float* __restrict__ outH, int M, int mode)
{
    extern __shared__ char smem_raw[];
    float* Wsm = (float*)smem_raw;                       // [128][136]
    float* Xs  = (float*)(smem_raw + 128 * WS_STRIDE * 4); // [128][68]

    const int tid  = threadIdx.x;
    const int lane = tid & 31;
    const int wi   = tid >> 5;        // warp id 0..7
    const int n0   = wi * 16;         // this warp's col base
    const int lq   = lane >> 2;       // lane/4: 0..7
    const int lr   = lane & 3;        // lane%4: 0..3

    // Stage W (tf32): 4096 float4 loads, 16 per thread.
#pragma unroll
    for (int i = 0; i < 16; i++) {
        int li = tid + i * 256;       // 0..4095
        int k  = li >> 5;             // 0..127
        int c4 = li & 31;             // 0..31
        float4 v = __ldg((const float4*)W + li);
        float* wp = Wsm + k * WS_STRIDE + c4 * 4;
        wp[0] = to_tf32(v.x); wp[1] = to_tf32(v.y);
        wp[2] = to_tf32(v.z); wp[3] = to_tf32(v.w);
    }

    for (int tile = blockIdx.x; tile < GEMM_TILES; tile += gridDim.x) {
        const int row0 = tile * 128;

        float acc[8][2][4];
#pragma unroll
        for (int mt = 0; mt < 8; mt++)
#pragma unroll
            for (int nt = 0; nt < 2; nt++)
#pragma unroll
                for (int c = 0; c < 4; c++) acc[mt][nt][c] = 0.0f;

        for (int chunk = 0; chunk < 2; chunk++) {
            const int k0 = chunk * 64;
            __syncthreads();   // Xs reusable / publishes W on first pass
            // Stage X chunk: 128 rows x 64 cols = 2048 float4s, 8/thread.
#pragma unroll
            for (int i = 0; i < 8; i++) {
                int li = tid + i * 256;    // 0..2047
                int r  = li >> 4;          // 0..127
                int c4 = li & 15;          // 0..15
                int gr = row0 + r;
                float4 v = make_float4(0.f, 0.f, 0.f, 0.f);
                if (gr < M) {
                    v = __ldg((const float4*)(A + (size_t)gr * 128 + k0) + c4);
                    if (mode) {
                        float di = __ldg(&dinv[gr]);
                        float4 bb = __ldg((const float4*)(biasIn + k0) + c4);
                        v.x = fmaxf(bb.x + di * v.x, 0.f);
                        v.y = fmaxf(bb.y + di * v.y, 0.f);
                        v.z = fmaxf(bb.z + di * v.z, 0.f);
                        v.w = fmaxf(bb.w + di * v.w, 0.f);
                    }
                }
                float* xr = Xs + r * XS_STRIDE + c4 * 4;
                xr[0] = to_tf32(v.x); xr[1] = to_tf32(v.y);
                xr[2] = to_tf32(v.z); xr[3] = to_tf32(v.w);
            }
            __syncthreads();

#pragma unroll
            for (int ks = 0; ks < 8; ks++) {
                const int kb = k0 + ks * 8;      // absolute k for W
                const int kx = ks * 8;           // k within X chunk
                // B fragments for this warp's two 8-col n-tiles
                float b[2][2];
#pragma unroll
                for (int nt = 0; nt < 2; nt++) {
                    int nc = n0 + nt * 8 + lq;
                    b[nt][0] = Wsm[(kb + lr) * WS_STRIDE + nc];
                    b[nt][1] = Wsm[(kb + 4 + lr) * WS_STRIDE + nc];
                }
#pragma unroll
                for (int mt = 0; mt < 8; mt++) {
                    int rbase = mt * 16;
                    float a0 = Xs[(rbase + lq) * XS_STRIDE + kx + lr];
                    float a1 = Xs[(rbase + lq + 8) * XS_STRIDE + kx + lr];
                    float a2 = Xs[(rbase + lq) * XS_STRIDE + kx + lr + 4];
                    float a3 = Xs[(rbase + lq + 8) * XS_STRIDE + kx + lr + 4];
                    mma_tf32(acc[mt][0][0], acc[mt][0][1], acc[mt][0][2], acc[mt][0][3],
                             a0, a1, a2, a3, b[0][0], b[0][1]);
                    mma_tf32(acc[mt][1][0], acc[mt][1][1], acc[mt][1][2], acc[mt][1][3],
                             a0, a1, a2, a3, b[1][0], b[1][1]);
                }
            }
        }

        // Epilogue: scale rows by dinv, store float2 pairs.
#pragma unroll
        for (int mt = 0; mt < 8; mt++) {
            int r1 = row0 + mt * 16 + lq;
            int r2 = r1 + 8;
            float d1 = (r1 < M) ? __ldg(&dinv[r1]) : 0.f;
            float d2 = (r2 < M) ? __ldg(&dinv[r2]) : 0.f;
#pragma unroll
            for (int nt = 0; nt < 2; nt++) {
                int col = n0 + nt * 8 + lr * 2;
                if (r1 < M)
                    *(float2*)(outH + (size_t)r1 * 128 + col) =
                        make_float2(acc[mt][nt][0] * d1, acc[mt][nt][1] * d1);
                if (r2 < M)
                    *(float2*)(outH + (size_t)r2 * 128 + col) =
                        make_float2(acc[mt][nt][2] * d2, acc[mt][nt][3] * d2);
            }
        }
    }
}

// ---------------------------------------------------------------------------
// Aggregate: one warp per node. sum = hs[n] + sum_{src in CSR[n]} hs[src].
//   mode 0: write raw sum to outSum
//   mode 1: v = relu(bg2 + dinv[n]*sum); red_add to gsum[batch[n]]  (fused pool)
// ---------------------------------------------------------------------------
__global__ __launch_bounds__(256)
void agg_kernel(const float4* __restrict__ hsv, const int* __restrict__ off,
                const int* __restrict__ csr, const float* __restrict__ dinv,
                const float* __restrict__ bias, const int* __restrict__ batch,
                float4* __restrict__ outSum, float* __restrict__ gsum, int mode)
{
    int w = (blockIdx.x * blockDim.x + threadIdx.x) >> 5;
    if (w >= NN) return;
    int lane = threadIdx.x & 31;
    int o0 = __ldg(&off[w]);
    int o1 = __ldg(&off[w + 1]);

    float4 acc = __ldg(&hsv[(size_t)w * 32 + lane]);   // self-loop term

    for (int j = o0; j < o1; j += 32) {
        int s = (j + lane < o1) ? __ldg(&csr[j + lane]) : 0;
        int n = min(32, o1 - j);
        for (int t = 0; t < n; t++) {
            int si = __shfl_sync(0xffffffff, s, t);
            float4 v = __ldg(&hsv[(size_t)si * 32 + lane]);
            acc.x += v.x; acc.y += v.y; acc.z += v.z; acc.w += v.w;
        }
    }

    if (mode == 0) {
        outSum[(size_t)w * 32 + lane] = acc;
    } else {
        float di = __ldg(&dinv[w]);
        float4 bb = __ldg((const float4*)bias + lane);
        acc.x = fmaxf(bb.x + di * acc.x, 0.f);
        acc.y = fmaxf(bb.y + di * acc.y, 0.f);
        acc.z = fmaxf(bb.z + di * acc.z, 0.f);
        acc.w = fmaxf(bb.w + di * acc.w, 0.f);
        int b = __ldg(&batch[w]);
        red_add_v4(gsum + (size_t)b * 128 + lane * 4, acc);
    }
}

// ---------------------------------------------------------------------------
// Fused head: 8 graphs per block, 128 threads (thread j owns output col j).
// ---------------------------------------------------------------------------
__global__ __launch_bounds__(128)
void final_kernel(const float* __restrict__ smiles,
                  const float* __restrict__ Ws1, const float* __restrict__ bs1,
                  const float* __restrict__ Ws2, const float* __restrict__ bs2,
                  const float* __restrict__ Wf,  const float* __restrict__ bf,
                  const float* __restrict__ Wo,  const float* __restrict__ bo,
                  const float* __restrict__ gsum, const int* __restrict__ cnt,
                  float* __restrict__ out) {
    __shared__ float sm[8][DS];
    __shared__ float s1[8][H];
    __shared__ float comb[8][2 * H];
    __shared__ float fz[8][H];

    const int b0 = blockIdx.x * 8;
    const int j = threadIdx.x;

    const float4* sp = (const float4*)(smiles + (size_t)b0 * DS);
#pragma unroll
    for (int i = 0; i < 12; i++)
        ((float4*)sm)[j + i * 128] = __ldg(sp + j + i * 128);
    __syncthreads();

    float a[8];
#pragma unroll
    for (int g = 0; g < 8; g++) a[g] = 0.f;
#pragma unroll 4
    for (int k = 0; k < DS; k++) {
        float w = __ldg(&Ws1[(size_t)k * H + j]);
#pragma unroll
        for (int g = 0; g < 8; g++) a[g] += sm[g][k] * w;
    }
    {
        float b1 = __ldg(&bs1[j]);
#pragma unroll
        for (int g = 0; g < 8; g++) s1[g][j] = fmaxf(a[g] + b1, 0.f);
    }
    __syncthreads();

#pragma unroll
    for (int g = 0; g < 8; g++) a[g] = 0.f;
#pragma unroll 4
    for (int k = 0; k < H; k++) {
        float w = __ldg(&Ws2[(size_t)k * H + j]);
#pragma unroll
        for (int g = 0; g < 8; g++) a[g] += s1[g][k] * w;
    }
    {
        float b2 = __ldg(&bs2[j]);
#pragma unroll
        for (int g = 0; g < 8; g++) {
            comb[g][j] = a[g] + b2;
            float c = (float)__ldg(&cnt[b0 + g]);
            comb[g][H + j] = __ldg(&gsum[(size_t)(b0 + g) * H + j]) / fmaxf(c, 1.f);
        }
    }
    __syncthreads();

#pragma unroll
    for (int g = 0; g < 8; g++) a[g] = 0.f;
#pragma unroll 4
    for (int k = 0; k < 2 * H; k++) {
        float w = __ldg(&Wf[(size_t)k * H + j]);
#pragma unroll
        for (int g = 0; g < 8; g++) a[g] += comb[g][k] * w;
    }
    {
        float bfv = __ldg(&bf[j]);
#pragma unroll
        for (int g = 0; g < 8; g++) fz[g][j] = fmaxf(a[g] + bfv, 0.f);
    }
    __syncthreads();

    if (j < 8 * NC) {
        int g = j / NC, c = j % NC;
        float s = __ldg(&bo[c]);
        for (int k = 0; k < H; k++)
            s += fz[g][k] * __ldg(&Wo[(size_t)k * NC + c]);
        out[(size_t)(b0 + g) * NC + c] = s;
    }
}

// ---------------------------------------------------------------------------
extern "C" void kernel_launch(void* const* d_in, const int* in_sizes, int n_in,
                              void* d_out, int out_size) {
    const float* smiles = (const float*)d_in[0];
    const float* x      = (const float*)d_in[1];
    const int*   ei     = (const int*)d_in[2];
    const int*   batch  = (const int*)d_in[3];
    const float* Ws1 = (const float*)d_in[4];
    const float* bs1 = (const float*)d_in[5];
    const float* Ws2 = (const float*)d_in[6];
    const float* bs2 = (const float*)d_in[7];
    const float* Wg1 = (const float*)d_in[8];
    const float* bg1 = (const float*)d_in[9];
    const float* Wg2 = (const float*)d_in[10];
    const float* bg2 = (const float*)d_in[11];
    const float* Wf  = (const float*)d_in[12];
    const float* bf  = (const float*)d_in[13];
    const float* Wo  = (const float*)d_in[14];
    const float* bo  = (const float*)d_in[15];
    float* out = (float*)d_out;

    float *bufA, *bufB, *dinv, *gsum;
    int *edeg, *off, *cursor, *csr, *blocksum, *blockoff, *cnt;
    cudaGetSymbolAddress((void**)&bufA, g_bufA);
    cudaGetSymbolAddress((void**)&bufB, g_bufB);
    cudaGetSymbolAddress((void**)&dinv, g_dinv);
    cudaGetSymbolAddress((void**)&edeg, g_edeg);
    cudaGetSymbolAddress((void**)&off,  g_off);
    cudaGetSymbolAddress((void**)&cursor, g_cursor);
    cudaGetSymbolAddress((void**)&csr,  g_csr);
    cudaGetSymbolAddress((void**)&blocksum, g_blocksum);
    cudaGetSymbolAddress((void**)&blockoff, g_blockoff);
    cudaGetSymbolAddress((void**)&gsum, g_gsum);
    cudaGetSymbolAddress((void**)&cnt,  g_cnt);

    cudaFuncSetAttribute(gemm_tc_kernel,
                         cudaFuncAttributeMaxDynamicSharedMemorySize, GEMM_SMEM);

    const int* src = ei;
    const int* dst = ei + NE;

    const int T = 256;

    // --- preprocessing: degrees, counts, CSR by dst ---
    prep_zero_kernel<<<(NG * H + T - 1) / T, T>>>(edeg, cnt, gsum, off);
    count_kernel<<<(NE + T - 1) / T, T>>>(dst, batch, edeg, cnt);
    dinv_kernel<<<(NN + T - 1) / T, T>>>(edeg, dinv);
    scan1_kernel<<<SCAN_NB, SCAN_B>>>(edeg, blocksum);
    scan2_kernel<<<1, SCAN_B>>>(blocksum, blockoff);
    scan3_kernel<<<SCAN_NB, SCAN_B>>>(edeg, blockoff, off, cursor);
    scatter_kernel<<<(NE + T - 1) / T, T>>>(src, dst, cursor, csr);

    const int GEMM_GRID = 296;     // 2 per SM, persistent
    const int AGG_GRID  = (NN * 32 + T - 1) / T;

    // --- GCN layer 1 ---
    gemm_tc_kernel<<<GEMM_GRID, 256, GEMM_SMEM>>>(x, Wg1, dinv, bg1, bufA, NN, 0);
    agg_kernel<<<AGG_GRID, T>>>((const float4*)bufA, off, csr, dinv, bg2, batch,
                                (float4*)bufB, gsum, 0);

    // --- GCN layer 2 (input transform relu(bg1 + dinv*sum1) inside GEMM) ---
    gemm_tc_kernel<<<GEMM_GRID, 256, GEMM_SMEM>>>(bufB, Wg2, dinv, bg1, bufA, NN, 1);
    // aggregate + fused pool into gsum
    agg_kernel<<<AGG_GRID, T>>>((const float4*)bufA, off, csr, dinv, bg2, batch,
                                (float4*)bufB, gsum, 1);

    // --- SMILES MLP + fusion + output head ---
    final_kernel<<<NG / 8, 128>>>(smiles, Ws1, bs1, Ws2, bs2, Wf, bf, Wo, bo,
                                  gsum, cnt, out);
}

// round 8
// speedup vs baseline: 1.6940x; 1.0093x over previous
#include <cuda_runtime.h>
#include <cuda_bf16.h>
#include <cstdint>

// Problem constants
constexpr int NN = 50000;    // nodes
constexpr int NE = 800000;   // edges
constexpr int NG = 1024;     // graphs
constexpr int H  = 128;      // hidden / node feature dim
constexpr int DS = 768;      // smiles dim
constexpr int NC = 12;       // classes

constexpr int SCAN_B  = 256;
constexpr int SCAN_NB = (NN + SCAN_B - 1) / SCAN_B;   // 196

// Scratch (device globals; no allocation allowed)
__device__ float g_bufA[(size_t)NN * H];   // hs (gather source, both layers)
__device__ float g_bufB[(size_t)NN * H];   // layer-1 aggregate sum
__device__ float g_dinv[NN];
__device__ int   g_edeg[NN];               // edge-only in-degree
__device__ int   g_off[NN + 1];            // CSR offsets (by dst)
__device__ int   g_cursor[NN];
__device__ int   g_csr[NE];                // src ids grouped by dst
__device__ int   g_blocksum[SCAN_B];
__device__ int   g_blockoff[SCAN_B];
__device__ float g_gsum[NG * H];
__device__ int   g_cnt[NG];

// ---------------------------------------------------------------------------
// Helpers
// ---------------------------------------------------------------------------
__device__ __forceinline__ float to_tf32(float x) {
    unsigned r;  // cvt to tf32 requires a .b32 destination register
    asm("cvt.rna.tf32.f32 %0, %1;" : "=r"(r) : "f"(x));
    return __uint_as_float(r);
}
__device__ __forceinline__ void mma_tf32(float& d0, float& d1, float& d2, float& d3,
                                         float a0, float a1, float a2, float a3,
                                         float b0, float b1) {
    asm volatile(
        "mma.sync.aligned.m16n8k8.row.col.f32.tf32.tf32.f32 "
        "{%0,%1,%2,%3}, {%4,%5,%6,%7}, {%8,%9}, {%0,%1,%2,%3};"
        : "+f"(d0), "+f"(d1), "+f"(d2), "+f"(d3)
        : "r"(__float_as_uint(a0)), "r"(__float_as_uint(a1)),
          "r"(__float_as_uint(a2)), "r"(__float_as_uint(a3)),
          "r"(__float_as_uint(b0)), "r"(__float_as_uint(b1)));
}
__device__ __forceinline__ void red_add_v4(float* p, float4 v) {
    asm volatile("red.global.add.v4.f32 [%0], {%1, %2, %3, %4};"
                 :: "l"(p), "f"(v.x), "f"(v.y), "f"(v.z), "f"(v.w)
                 : "memory");
}
__device__ __forceinline__ void acc4(float4& a, float4 v) {
    a.x += v.x; a.y += v.y; a.z += v.z; a.w += v.w;
}

// ---------------------------------------------------------------------------
// K0: zero/init
// ---------------------------------------------------------------------------
__global__ void prep_zero_kernel(int* __restrict__ edeg, int* __restrict__ cnt,
                                 float* __restrict__ gsum, int* __restrict__ off) {
    int i = blockIdx.x * blockDim.x + threadIdx.x;
    if (i < NN) edeg[i] = 0;
    if (i < NG) cnt[i] = 0;
    if (i < NG * H) gsum[i] = 0.0f;
    if (i == 0) off[NN] = NE;
}

// ---------------------------------------------------------------------------
// K1: in-degree (edges only) + node counts per graph
// ---------------------------------------------------------------------------
__global__ void count_kernel(const int* __restrict__ dst, const int* __restrict__ batch,
                             int* __restrict__ edeg, int* __restrict__ cnt) {
    int i = blockIdx.x * blockDim.x + threadIdx.x;
    if (i < NE) atomicAdd(&edeg[dst[i]], 1);
    if (i < NN) atomicAdd(&cnt[batch[i]], 1);
}

// ---------------------------------------------------------------------------
// K2: dinv = rsqrt(edeg + 1)
// ---------------------------------------------------------------------------
__global__ void dinv_kernel(const int* __restrict__ edeg, float* __restrict__ dinv) {
    int i = blockIdx.x * blockDim.x + threadIdx.x;
    if (i < NN) dinv[i] = rsqrtf((float)(edeg[i] + 1));
}

// ---------------------------------------------------------------------------
// Scan stage 1: per-block sums of edeg
// ---------------------------------------------------------------------------
__global__ __launch_bounds__(SCAN_B)
void scan1_kernel(const int* __restrict__ edeg, int* __restrict__ blocksum) {
    __shared__ int sh[SCAN_B];
    int t = threadIdx.x;
    int i = blockIdx.x * SCAN_B + t;
    sh[t] = (i < NN) ? edeg[i] : 0;
    __syncthreads();
    for (int d = SCAN_B / 2; d > 0; d >>= 1) {
        if (t < d) sh[t] += sh[t + d];
        __syncthreads();
    }
    if (t == 0) blocksum[blockIdx.x] = sh[0];
}

// ---------------------------------------------------------------------------
// Scan stage 2: single-block exclusive scan of block sums
// ---------------------------------------------------------------------------
__global__ __launch_bounds__(SCAN_B)
void scan2_kernel(const int* __restrict__ blocksum, int* __restrict__ blockoff) {
    __shared__ int sh[SCAN_B];
    int t = threadIdx.x;
    int v = (t < SCAN_NB) ? blocksum[t] : 0;
    sh[t] = v;
    __syncthreads();
    for (int d = 1; d < SCAN_B; d <<= 1) {
        int add = (t >= d) ? sh[t - d] : 0;
        __syncthreads();
        sh[t] += add;
        __syncthreads();
    }
    blockoff[t] = sh[t] - v;   // exclusive
}

// ---------------------------------------------------------------------------
// Scan stage 3: per-element exclusive offsets; init cursor
// ---------------------------------------------------------------------------
__global__ __launch_bounds__(SCAN_B)
void scan3_kernel(const int* __restrict__ edeg, const int* __restrict__ blockoff,
                  int* __restrict__ off, int* __restrict__ cursor) {
    __shared__ int wsum[8], wbase[8];
    int t = threadIdx.x;
    int lane = t & 31, wid = t >> 5;
    int i = blockIdx.x * SCAN_B + t;
    int v = (i < NN) ? edeg[i] : 0;
    int x = v;
#pragma unroll
    for (int d = 1; d < 32; d <<= 1) {
        int y = __shfl_up_sync(0xffffffff, x, d);
        if (lane >= d) x += y;
    }
    if (lane == 31) wsum[wid] = x;
    __syncthreads();
    if (t == 0) {
        int run = 0;
#pragma unroll
        for (int k = 0; k < 8; k++) { wbase[k] = run; run += wsum[k]; }
    }
    __syncthreads();
    if (i < NN) {
        int e = blockoff[blockIdx.x] + wbase[wid] + (x - v);
        off[i] = e;
        cursor[i] = e;
    }
}

// ---------------------------------------------------------------------------
// K3: scatter edges into CSR (grouped by dst)
// ---------------------------------------------------------------------------
__global__ void scatter_kernel(const int* __restrict__ src, const int* __restrict__ dst,
                               int* __restrict__ cursor, int* __restrict__ csr) {
    int i = blockIdx.x * blockDim.x + threadIdx.x;
    if (i >= NE) return;
    int d = dst[i];
    int p = atomicAdd(&cursor[d], 1);
    csr[p] = src[i];
}

// ---------------------------------------------------------------------------
// Persistent tf32 tensor-core GEMM:
//   hs[M,128] = dinv[row] * (T(A)[M,128] @ W[128,128])
//   mode 0: T(a) = a
//   mode 1: T(a) = relu(biasIn[k] + dinv[row]*a)
// ---------------------------------------------------------------------------
constexpr int WS_STRIDE = 136;
constexpr int XS_STRIDE = 68;
constexpr int GEMM_SMEM = 128 * WS_STRIDE * 4 + 128 * XS_STRIDE * 4;  // 104448
constexpr int GEMM_TILES = (NN + 127) / 128;      // 391

__global__ __launch_bounds__(256, 2)
void gemm_tc_kernel(const float* __restrict__ A, const float* __restrict__ W,
                    const float* __restrict__ dinv, const float* __restrict__ biasIn,
                    float* __restrict__ outH, int M, int mode)
{
    extern __shared__ char smem_raw[];
    float* Wsm = (float*)smem_raw;                       // [128][136]
    float* Xs  = (float*)(smem_raw + 128 * WS_STRIDE * 4); // [128][68]

    const int tid  = threadIdx.x;
    const int lane = tid & 31;
    const int wi   = tid >> 5;        // warp id 0..7
    const int n0   = wi * 16;         // this warp's col base
    const int lq   = lane >> 2;       // lane/4: 0..7
    const int lr   = lane & 3;        // lane%4: 0..3

    // Stage W (tf32): 4096 float4 loads, 16 per thread.
#pragma unroll
    for (int i = 0; i < 16; i++) {
        int li = tid + i * 256;       // 0..4095
        int k  = li >> 5;             // 0..127
        int c4 = li & 31;             // 0..31
        float4 v = __ldg((const float4*)W + li);
        float* wp = Wsm + k * WS_STRIDE + c4 * 4;
        wp[0] = to_tf32(v.x); wp[1] = to_tf32(v.y);
        wp[2] = to_tf32(v.z); wp[3] = to_tf32(v.w);
    }

    for (int tile = blockIdx.x; tile < GEMM_TILES; tile += gridDim.x) {
        const int row0 = tile * 128;

        float acc[8][2][4];
#pragma unroll
        for (int mt = 0; mt < 8; mt++)
#pragma unroll
            for (int nt = 0; nt < 2; nt++)
#pragma unroll
                for (int c = 0; c < 4; c++) acc[mt][nt][c] = 0.0f;

        for (int chunk = 0; chunk < 2; chunk++) {
            const int k0 = chunk * 64;
            __syncthreads();   // Xs reusable / publishes W on first pass
            // Stage X chunk: 128 rows x 64 cols = 2048 float4s, 8/thread.
#pragma unroll
            for (int i = 0; i < 8; i++) {
                int li = tid + i * 256;    // 0..2047
                int r  = li >> 4;          // 0..127
                int c4 = li & 15;          // 0..15
                int gr = row0 + r;
                float4 v = make_float4(0.f, 0.f, 0.f, 0.f);
                if (gr < M) {
                    v = __ldg((const float4*)(A + (size_t)gr * 128 + k0) + c4);
                    if (mode) {
                        float di = __ldg(&dinv[gr]);
                        float4 bb = __ldg((const float4*)(biasIn + k0) + c4);
                        v.x = fmaxf(bb.x + di * v.x, 0.f);
                        v.y = fmaxf(bb.y + di * v.y, 0.f);
                        v.z = fmaxf(bb.z + di * v.z, 0.f);
                        v.w = fmaxf(bb.w + di * v.w, 0.f);
                    }
                }
                float* xr = Xs + r * XS_STRIDE + c4 * 4;
                xr[0] = to_tf32(v.x); xr[1] = to_tf32(v.y);
                xr[2] = to_tf32(v.z); xr[3] = to_tf32(v.w);
            }
            __syncthreads();

#pragma unroll
            for (int ks = 0; ks < 8; ks++) {
                const int kb = k0 + ks * 8;      // absolute k for W
                const int kx = ks * 8;           // k within X chunk
                float b[2][2];
#pragma unroll
                for (int nt = 0; nt < 2; nt++) {
                    int nc = n0 + nt * 8 + lq;
                    b[nt][0] = Wsm[(kb + lr) * WS_STRIDE + nc];
                    b[nt][1] = Wsm[(kb + 4 + lr) * WS_STRIDE + nc];
                }
#pragma unroll
                for (int mt = 0; mt < 8; mt++) {
                    int rbase = mt * 16;
                    float a0 = Xs[(rbase + lq) * XS_STRIDE + kx + lr];
                    float a1 = Xs[(rbase + lq + 8) * XS_STRIDE + kx + lr];
                    float a2 = Xs[(rbase + lq) * XS_STRIDE + kx + lr + 4];
                    float a3 = Xs[(rbase + lq + 8) * XS_STRIDE + kx + lr + 4];
                    mma_tf32(acc[mt][0][0], acc[mt][0][1], acc[mt][0][2], acc[mt][0][3],
                             a0, a1, a2, a3, b[0][0], b[0][1]);
                    mma_tf32(acc[mt][1][0], acc[mt][1][1], acc[mt][1][2], acc[mt][1][3],
                             a0, a1, a2, a3, b[1][0], b[1][1]);
                }
            }
        }

        // Epilogue: scale rows by dinv, store float2 pairs.
#pragma unroll
        for (int mt = 0; mt < 8; mt++) {
            int r1 = row0 + mt * 16 + lq;
            int r2 = r1 + 8;
            float d1 = (r1 < M) ? __ldg(&dinv[r1]) : 0.f;
            float d2 = (r2 < M) ? __ldg(&dinv[r2]) : 0.f;
#pragma unroll
            for (int nt = 0; nt < 2; nt++) {
                int col = n0 + nt * 8 + lr * 2;
                if (r1 < M)
                    *(float2*)(outH + (size_t)r1 * 128 + col) =
                        make_float2(acc[mt][nt][0] * d1, acc[mt][nt][1] * d1);
                if (r2 < M)
                    *(float2*)(outH + (size_t)r2 * 128 + col) =
                        make_float2(acc[mt][nt][2] * d2, acc[mt][nt][3] * d2);
            }
        }
    }
}

// ---------------------------------------------------------------------------
// Aggregate: one warp per node. sum = hs[n] + sum_{src in CSR[n]} hs[src].
// CSR indices are warp-uniform: every lane __ldg's csr[j] directly (broadcast
// load), unrolled x4 so 4 independent 512B row-gathers are in flight.
//   mode 0: write raw sum to outSum
//   mode 1: v = relu(bg2 + dinv[n]*sum); red_add to gsum[batch[n]]  (fused pool)
// ---------------------------------------------------------------------------
__global__ __launch_bounds__(256)
void agg_kernel(const float4* __restrict__ hsv, const int* __restrict__ off,
                const int* __restrict__ csr, const float* __restrict__ dinv,
                const float* __restrict__ bias, const int* __restrict__ batch,
                float4* __restrict__ outSum, float* __restrict__ gsum, int mode)
{
    int w = (blockIdx.x * blockDim.x + threadIdx.x) >> 5;
    if (w >= NN) return;
    int lane = threadIdx.x & 31;
    int o0 = __ldg(&off[w]);
    int o1 = __ldg(&off[w + 1]);

    float4 acc0 = __ldg(&hsv[(size_t)w * 32 + lane]);   // self-loop term
    float4 acc1 = make_float4(0.f, 0.f, 0.f, 0.f);

    int j = o0;
    for (; j + 4 <= o1; j += 4) {
        int s0 = __ldg(&csr[j]);
        int s1 = __ldg(&csr[j + 1]);
        int s2 = __ldg(&csr[j + 2]);
        int s3 = __ldg(&csr[j + 3]);
        float4 v0 = __ldg(&hsv[(size_t)s0 * 32 + lane]);
        float4 v1 = __ldg(&hsv[(size_t)s1 * 32 + lane]);
        float4 v2 = __ldg(&hsv[(size_t)s2 * 32 + lane]);
        float4 v3 = __ldg(&hsv[(size_t)s3 * 32 + lane]);
        acc4(acc0, v0); acc4(acc1, v1); acc4(acc0, v2); acc4(acc1, v3);
    }
    for (; j < o1; j++) {
        int s = __ldg(&csr[j]);
        acc4(acc0, __ldg(&hsv[(size_t)s * 32 + lane]));
    }
    acc4(acc0, acc1);

    if (mode == 0) {
        outSum[(size_t)w * 32 + lane] = acc0;
    } else {
        float di = __ldg(&dinv[w]);
        float4 bb = __ldg((const float4*)bias + lane);
        acc0.x = fmaxf(bb.x + di * acc0.x, 0.f);
        acc0.y = fmaxf(bb.y + di * acc0.y, 0.f);
        acc0.z = fmaxf(bb.z + di * acc0.z, 0.f);
        acc0.w = fmaxf(bb.w + di * acc0.w, 0.f);
        int b = __ldg(&batch[w]);
        red_add_v4(gsum + (size_t)b * 128 + lane * 4, acc0);
    }
}

// ---------------------------------------------------------------------------
// Fused head: 8 graphs per block, 128 threads (thread j owns output col j).
// ---------------------------------------------------------------------------
__global__ __launch_bounds__(128)
void final_kernel(const float* __restrict__ smiles,
                  const float* __restrict__ Ws1, const float* __restrict__ bs1,
                  const float* __restrict__ Ws2, const float* __restrict__ bs2,
                  const float* __restrict__ Wf,  const float* __restrict__ bf,
                  const float* __restrict__ Wo,  const float* __restrict__ bo,
                  const float* __restrict__ gsum, const int* __restrict__ cnt,
                  float* __restrict__ out) {
    __shared__ float sm[8][DS];
    __shared__ float s1[8][H];
    __shared__ float comb[8][2 * H];
    __shared__ float fz[8][H];

    const int b0 = blockIdx.x * 8;
    const int j = threadIdx.x;

    const float4* sp = (const float4*)(smiles + (size_t)b0 * DS);
#pragma unroll
    for (int i = 0; i < 12; i++)
        ((float4*)sm)[j + i * 128] = __ldg(sp + j + i * 128);
    __syncthreads();

    float a[8];
#pragma unroll
    for (int g = 0; g < 8; g++) a[g] = 0.f;
#pragma unroll 4
    for (int k = 0; k < DS; k++) {
        float w = __ldg(&Ws1[(size_t)k * H + j]);
#pragma unroll
        for (int g = 0; g < 8; g++) a[g] += sm[g][k] * w;
    }
    {
        float b1 = __ldg(&bs1[j]);
#pragma unroll
        for (int g = 0; g < 8; g++) s1[g][j] = fmaxf(a[g] + b1, 0.f);
    }
    __syncthreads();

#pragma unroll
    for (int g = 0; g < 8; g++) a[g] = 0.f;
#pragma unroll 4
    for (int k = 0; k < H; k++) {
        float w = __ldg(&Ws2[(size_t)k * H + j]);
#pragma unroll
        for (int g = 0; g < 8; g++) a[g] += s1[g][k] * w;
    }
    {
        float b2 = __ldg(&bs2[j]);
#pragma unroll
        for (int g = 0; g < 8; g++) {
            comb[g][j] = a[g] + b2;
            float c = (float)__ldg(&cnt[b0 + g]);
            comb[g][H + j] = __ldg(&gsum[(size_t)(b0 + g) * H + j]) / fmaxf(c, 1.f);
        }
    }
    __syncthreads();

#pragma unroll
    for (int g = 0; g < 8; g++) a[g] = 0.f;
#pragma unroll 4
    for (int k = 0; k < 2 * H; k++) {
        float w = __ldg(&Wf[(size_t)k * H + j]);
#pragma unroll
        for (int g = 0; g < 8; g++) a[g] += comb[g][k] * w;
    }
    {
        float bfv = __ldg(&bf[j]);
#pragma unroll
        for (int g = 0; g < 8; g++) fz[g][j] = fmaxf(a[g] + bfv, 0.f);
    }
    __syncthreads();

    if (j < 8 * NC) {
        int g = j / NC, c = j % NC;
        float s = __ldg(&bo[c]);
        for (int k = 0; k < H; k++)
            s += fz[g][k] * __ldg(&Wo[(size_t)k * NC + c]);
        out[(size_t)(b0 + g) * NC + c] = s;
    }
}

// ---------------------------------------------------------------------------
extern "C" void kernel_launch(void* const* d_in, const int* in_sizes, int n_in,
                              void* d_out, int out_size) {
    const float* smiles = (const float*)d_in[0];
    const float* x      = (const float*)d_in[1];
    const int*   ei     = (const int*)d_in[2];
    const int*   batch  = (const int*)d_in[3];
    const float* Ws1 = (const float*)d_in[4];
    const float* bs1 = (const float*)d_in[5];
    const float* Ws2 = (const float*)d_in[6];
    const float* bs2 = (const float*)d_in[7];
    const float* Wg1 = (const float*)d_in[8];
    const float* bg1 = (const float*)d_in[9];
    const float* Wg2 = (const float*)d_in[10];
    const float* bg2 = (const float*)d_in[11];
    const float* Wf  = (const float*)d_in[12];
    const float* bf  = (const float*)d_in[13];
    const float* Wo  = (const float*)d_in[14];
    const float* bo  = (const float*)d_in[15];
    float* out = (float*)d_out;

    float *bufA, *bufB, *dinv, *gsum;
    int *edeg, *off, *cursor, *csr, *blocksum, *blockoff, *cnt;
    cudaGetSymbolAddress((void**)&bufA, g_bufA);
    cudaGetSymbolAddress((void**)&bufB, g_bufB);
    cudaGetSymbolAddress((void**)&dinv, g_dinv);
    cudaGetSymbolAddress((void**)&edeg, g_edeg);
    cudaGetSymbolAddress((void**)&off,  g_off);
    cudaGetSymbolAddress((void**)&cursor, g_cursor);
    cudaGetSymbolAddress((void**)&csr,  g_csr);
    cudaGetSymbolAddress((void**)&blocksum, g_blocksum);
    cudaGetSymbolAddress((void**)&blockoff, g_blockoff);
    cudaGetSymbolAddress((void**)&gsum, g_gsum);
    cudaGetSymbolAddress((void**)&cnt,  g_cnt);

    cudaFuncSetAttribute(gemm_tc_kernel,
                         cudaFuncAttributeMaxDynamicSharedMemorySize, GEMM_SMEM);

    const int* src = ei;
    const int* dst = ei + NE;

    const int T = 256;

    // --- preprocessing: degrees, counts, CSR by dst ---
    prep_zero_kernel<<<(NG * H + T - 1) / T, T>>>(edeg, cnt, gsum, off);
    count_kernel<<<(NE + T - 1) / T, T>>>(dst, batch, edeg, cnt);
    dinv_kernel<<<(NN + T - 1) / T, T>>>(edeg, dinv);
    scan1_kernel<<<SCAN_NB, SCAN_B>>>(edeg, blocksum);
    scan2_kernel<<<1, SCAN_B>>>(blocksum, blockoff);
    scan3_kernel<<<SCAN_NB, SCAN_B>>>(edeg, blockoff, off, cursor);
    scatter_kernel<<<(NE + T - 1) / T, T>>>(src, dst, cursor, csr);

    const int GEMM_GRID = 296;     // 2 per SM, persistent
    const int AGG_GRID  = (NN * 32 + T - 1) / T;

    // --- GCN layer 1 ---
    gemm_tc_kernel<<<GEMM_GRID, 256, GEMM_SMEM>>>(x, Wg1, dinv, bg1, bufA, NN, 0);
    agg_kernel<<<AGG_GRID, T>>>((const float4*)bufA, off, csr, dinv, bg2, batch,
                                (float4*)bufB, gsum, 0);

    // --- GCN layer 2 (input transform relu(bg1 + dinv*sum1) inside GEMM) ---
    gemm_tc_kernel<<<GEMM_GRID, 256, GEMM_SMEM>>>(bufB, Wg2, dinv, bg1, bufA, NN, 1);
    // aggregate + fused pool into gsum
    agg_kernel<<<AGG_GRID, T>>>((const float4*)bufA, off, csr, dinv, bg2, batch,
                                (float4*)bufB, gsum, 1);

    // --- SMILES MLP + fusion + output head ---
    final_kernel<<<NG / 8, 128>>>(smiles, Ws1, bs1, Ws2, bs2, Wf, bf, Wo, bo,
                                  gsum, cnt, out);
}

// round 10
// speedup vs baseline: 2.2475x; 1.3267x over previous
#include <cuda_runtime.h>
#include <cuda_bf16.h>
#include <cuda_fp16.h>
#include <cstdint>

// Problem constants
constexpr int NN = 50000;    // nodes
constexpr int NE = 800000;   // edges
constexpr int NG = 1024;     // graphs
constexpr int H  = 128;      // hidden / node feature dim
constexpr int DS = 768;      // smiles dim
constexpr int NC = 12;       // classes

constexpr int SCAN_B  = 256;
constexpr int SCAN_NB = (NN + SCAN_B - 1) / SCAN_B;   // 196

// Scratch (device globals; no allocation allowed)
__device__ __half g_hsH[(size_t)NN * H];   // fp16 gather table (both layers)
__device__ float  g_bufB[(size_t)NN * H];  // layer-1 aggregate sum (fp32)
__device__ float  g_dinv[NN];
__device__ int    g_edeg[NN];              // edge-only in-degree
__device__ int    g_off[NN + 1];           // CSR offsets (by dst)
__device__ int    g_cursor[NN];
__device__ int    g_csr[NE];               // src ids grouped by dst
__device__ int    g_blocksum[SCAN_B];
__device__ int    g_blockoff[SCAN_B];
__device__ float  g_gsum[NG * H];
__device__ int    g_cnt[NG];

// ---------------------------------------------------------------------------
// Helpers
// ---------------------------------------------------------------------------
__device__ __forceinline__ float to_tf32(float x) {
    unsigned r;  // cvt to tf32 requires a .b32 destination register
    asm("cvt.rna.tf32.f32 %0, %1;" : "=r"(r) : "f"(x));
    return __uint_as_float(r);
}
__device__ __forceinline__ void mma_tf32(float& d0, float& d1, float& d2, float& d3,
                                         float a0, float a1, float a2, float a3,
                                         float b0, float b1) {
    asm volatile(
        "mma.sync.aligned.m16n8k8.row.col.f32.tf32.tf32.f32 "
        "{%0,%1,%2,%3}, {%4,%5,%6,%7}, {%8,%9}, {%0,%1,%2,%3};"
        : "+f"(d0), "+f"(d1), "+f"(d2), "+f"(d3)
        : "r"(__float_as_uint(a0)), "r"(__float_as_uint(a1)),
          "r"(__float_as_uint(a2)), "r"(__float_as_uint(a3)),
          "r"(__float_as_uint(b0)), "r"(__float_as_uint(b1)));
}
__device__ __forceinline__ void red_add_v4(float* p, float4 v) {
    asm volatile("red.global.add.v4.f32 [%0], {%1, %2, %3, %4};"
                 :: "l"(p), "f"(v.x), "f"(v.y), "f"(v.z), "f"(v.w)
                 : "memory");
}
// Accumulate 4 halves (as uint2) into a float4 accumulator.
__device__ __forceinline__ void acc_h4(float4& a, uint2 u) {
    __half2 h0 = *reinterpret_cast<__half2*>(&u.x);
    __half2 h1 = *reinterpret_cast<__half2*>(&u.y);
    float2 f0 = __half22float2(h0);
    float2 f1 = __half22float2(h1);
    a.x += f0.x; a.y += f0.y; a.z += f1.x; a.w += f1.y;
}

// ---------------------------------------------------------------------------
// K0: zero/init
// ---------------------------------------------------------------------------
__global__ void prep_zero_kernel(int* __restrict__ edeg, int* __restrict__ cnt,
                                 float* __restrict__ gsum, int* __restrict__ off) {
    int i = blockIdx.x * blockDim.x + threadIdx.x;
    if (i < NN) edeg[i] = 0;
    if (i < NG) cnt[i] = 0;
    if (i < NG * H) gsum[i] = 0.0f;
    if (i == 0) off[NN] = NE;
}

// ---------------------------------------------------------------------------
// K1: in-degree (edges only) + node counts per graph
// ---------------------------------------------------------------------------
__global__ void count_kernel(const int* __restrict__ dst, const int* __restrict__ batch,
                             int* __restrict__ edeg, int* __restrict__ cnt) {
    int i = blockIdx.x * blockDim.x + threadIdx.x;
    if (i < NE) atomicAdd(&edeg[dst[i]], 1);
    if (i < NN) atomicAdd(&cnt[batch[i]], 1);
}

// ---------------------------------------------------------------------------
// K2: dinv = rsqrt(edeg + 1)
// ---------------------------------------------------------------------------
__global__ void dinv_kernel(const int* __restrict__ edeg, float* __restrict__ dinv) {
    int i = blockIdx.x * blockDim.x + threadIdx.x;
    if (i < NN) dinv[i] = rsqrtf((float)(edeg[i] + 1));
}

// ---------------------------------------------------------------------------
// Scan stage 1: per-block sums of edeg
// ---------------------------------------------------------------------------
__global__ __launch_bounds__(SCAN_B)
void scan1_kernel(const int* __restrict__ edeg, int* __restrict__ blocksum) {
    __shared__ int sh[SCAN_B];
    int t = threadIdx.x;
    int i = blockIdx.x * SCAN_B + t;
    sh[t] = (i < NN) ? edeg[i] : 0;
    __syncthreads();
    for (int d = SCAN_B / 2; d > 0; d >>= 1) {
        if (t < d) sh[t] += sh[t + d];
        __syncthreads();
    }
    if (t == 0) blocksum[blockIdx.x] = sh[0];
}

// ---------------------------------------------------------------------------
// Scan stage 2: single-block exclusive scan of block sums
// ---------------------------------------------------------------------------
__global__ __launch_bounds__(SCAN_B)
void scan2_kernel(const int* __restrict__ blocksum, int* __restrict__ blockoff) {
    __shared__ int sh[SCAN_B];
    int t = threadIdx.x;
    int v = (t < SCAN_NB) ? blocksum[t] : 0;
    sh[t] = v;
    __syncthreads();
    for (int d = 1; d < SCAN_B; d <<= 1) {
        int add = (t >= d) ? sh[t - d] : 0;
        __syncthreads();
        sh[t] += add;
        __syncthreads();
    }
    blockoff[t] = sh[t] - v;   // exclusive
}

// ---------------------------------------------------------------------------
// Scan stage 3: per-element exclusive offsets; init cursor
// ---------------------------------------------------------------------------
__global__ __launch_bounds__(SCAN_B)
void scan3_kernel(const int* __restrict__ edeg, const int* __restrict__ blockoff,
                  int* __restrict__ off, int* __restrict__ cursor) {
    __shared__ int wsum[8], wbase[8];
    int t = threadIdx.x;
    int lane = t & 31, wid = t >> 5;
    int i = blockIdx.x * SCAN_B + t;
    int v = (i < NN) ? edeg[i] : 0;
    int x = v;
#pragma unroll
    for (int d = 1; d < 32; d <<= 1) {
        int y = __shfl_up_sync(0xffffffff, x, d);
        if (lane >= d) x += y;
    }
    if (lane == 31) wsum[wid] = x;
    __syncthreads();
    if (t == 0) {
        int run = 0;
#pragma unroll
        for (int k = 0; k < 8; k++) { wbase[k] = run; run += wsum[k]; }
    }
    __syncthreads();
    if (i < NN) {
        int e = blockoff[blockIdx.x] + wbase[wid] + (x - v);
        off[i] = e;
        cursor[i] = e;
    }
}

// ---------------------------------------------------------------------------
// K3: scatter edges into CSR (grouped by dst)
// ---------------------------------------------------------------------------
__global__ void scatter_kernel(const int* __restrict__ src, const int* __restrict__ dst,
                               int* __restrict__ cursor, int* __restrict__ csr) {
    int i = blockIdx.x * blockDim.x + threadIdx.x;
    if (i >= NE) return;
    int d = dst[i];
    int p = atomicAdd(&cursor[d], 1);
    csr[p] = src[i];
}

// ---------------------------------------------------------------------------
// Persistent tf32 tensor-core GEMM:
//   hsH[M,128] = fp16( dinv[row] * (T(A)[M,128] @ W[128,128]) )
//   mode 0: T(a) = a
//   mode 1: T(a) = relu(biasIn[k] + dinv[row]*a)
// ---------------------------------------------------------------------------
constexpr int WS_STRIDE = 136;
constexpr int XS_STRIDE = 68;
constexpr int GEMM_SMEM = 128 * WS_STRIDE * 4 + 128 * XS_STRIDE * 4;  // 104448
constexpr int GEMM_TILES = (NN + 127) / 128;      // 391

__global__ __launch_bounds__(256, 2)
void gemm_tc_kernel(const float* __restrict__ A, const float* __restrict__ W,
                    const float* __restrict__ dinv, const float* __restrict__ biasIn,
                    __half* __restrict__ outH, int M, int mode)
{
    extern __shared__ char smem_raw[];
    float* Wsm = (float*)smem_raw;                       // [128][136]
    float* Xs  = (float*)(smem_raw + 128 * WS_STRIDE * 4); // [128][68]

    const int tid  = threadIdx.x;
    const int lane = tid & 31;
    const int wi   = tid >> 5;        // warp id 0..7
    const int n0   = wi * 16;         // this warp's col base
    const int lq   = lane >> 2;       // lane/4: 0..7
    const int lr   = lane & 3;        // lane%4: 0..3

    // Stage W (tf32): 4096 float4 loads, 16 per thread.
#pragma unroll
    for (int i = 0; i < 16; i++) {
        int li = tid + i * 256;       // 0..4095
        int k  = li >> 5;             // 0..127
        int c4 = li & 31;             // 0..31
        float4 v = __ldg((const float4*)W + li);
        float* wp = Wsm + k * WS_STRIDE + c4 * 4;
        wp[0] = to_tf32(v.x); wp[1] = to_tf32(v.y);
        wp[2] = to_tf32(v.z); wp[3] = to_tf32(v.w);
    }

    for (int tile = blockIdx.x; tile < GEMM_TILES; tile += gridDim.x) {
        const int row0 = tile * 128;

        float acc[8][2][4];
#pragma unroll
        for (int mt = 0; mt < 8; mt++)
#pragma unroll
            for (int nt = 0; nt < 2; nt++)
#pragma unroll
                for (int c = 0; c < 4; c++) acc[mt][nt][c] = 0.0f;

        for (int chunk = 0; chunk < 2; chunk++) {
            const int k0 = chunk * 64;
            __syncthreads();   // Xs reusable / publishes W on first pass
            // Stage X chunk: 128 rows x 64 cols = 2048 float4s, 8/thread.
#pragma unroll
            for (int i = 0; i < 8; i++) {
                int li = tid + i * 256;    // 0..2047
                int r  = li >> 4;          // 0..127
                int c4 = li & 15;          // 0..15
                int gr = row0 + r;
                float4 v = make_float4(0.f, 0.f, 0.f, 0.f);
                if (gr < M) {
                    v = __ldg((const float4*)(A + (size_t)gr * 128 + k0) + c4);
                    if (mode) {
                        float di = __ldg(&dinv[gr]);
                        float4 bb = __ldg((const float4*)(biasIn + k0) + c4);
                        v.x = fmaxf(bb.x + di * v.x, 0.f);
                        v.y = fmaxf(bb.y + di * v.y, 0.f);
                        v.z = fmaxf(bb.z + di * v.z, 0.f);
                        v.w = fmaxf(bb.w + di * v.w, 0.f);
                    }
                }
                float* xr = Xs + r * XS_STRIDE + c4 * 4;
                xr[0] = to_tf32(v.x); xr[1] = to_tf32(v.y);
                xr[2] = to_tf32(v.z); xr[3] = to_tf32(v.w);
            }
            __syncthreads();

#pragma unroll
            for (int ks = 0; ks < 8; ks++) {
                const int kb = k0 + ks * 8;      // absolute k for W
                const int kx = ks * 8;           // k within X chunk
                float b[2][2];
#pragma unroll
                for (int nt = 0; nt < 2; nt++) {
                    int nc = n0 + nt * 8 + lq;
                    b[nt][0] = Wsm[(kb + lr) * WS_STRIDE + nc];
                    b[nt][1] = Wsm[(kb + 4 + lr) * WS_STRIDE + nc];
                }
#pragma unroll
                for (int mt = 0; mt < 8; mt++) {
                    int rbase = mt * 16;
                    float a0 = Xs[(rbase + lq) * XS_STRIDE + kx + lr];
                    float a1 = Xs[(rbase + lq + 8) * XS_STRIDE + kx + lr];
                    float a2 = Xs[(rbase + lq) * XS_STRIDE + kx + lr + 4];
                    float a3 = Xs[(rbase + lq + 8) * XS_STRIDE + kx + lr + 4];
                    mma_tf32(acc[mt][0][0], acc[mt][0][1], acc[mt][0][2], acc[mt][0][3],
                             a0, a1, a2, a3, b[0][0], b[0][1]);
                    mma_tf32(acc[mt][1][0], acc[mt][1][1], acc[mt][1][2], acc[mt][1][3],
                             a0, a1, a2, a3, b[1][0], b[1][1]);
                }
            }
        }

        // Epilogue: scale rows by dinv, store fp16 pairs.
#pragma unroll
        for (int mt = 0; mt < 8; mt++) {
            int r1 = row0 + mt * 16 + lq;
            int r2 = r1 + 8;
            float d1 = (r1 < M) ? __ldg(&dinv[r1]) : 0.f;
            float d2 = (r2 < M) ? __ldg(&dinv[r2]) : 0.f;
#pragma unroll
            for (int nt = 0; nt < 2; nt++) {
                int col = n0 + nt * 8 + lr * 2;
                if (r1 < M)
                    *(__half2*)(outH + (size_t)r1 * 128 + col) =
                        __floats2half2_rn(acc[mt][nt][0] * d1, acc[mt][nt][1] * d1);
                if (r2 < M)
                    *(__half2*)(outH + (size_t)r2 * 128 + col) =
                        __floats2half2_rn(acc[mt][nt][2] * d2, acc[mt][nt][3] * d2);
            }
        }
    }
}

// ---------------------------------------------------------------------------
// Aggregate: one warp per node, fp16 gather (256B/row), fp32 accumulation.
// sum = hs[n] + sum_{src in CSR[n]} hs[src]; lane owns cols lane*4..lane*4+3.
//   mode 0: write raw fp32 sum to outSum
//   mode 1: v = relu(bg2 + dinv[n]*sum); red_add to gsum[batch[n]]  (fused pool)
// ---------------------------------------------------------------------------
__global__ __launch_bounds__(256)
void agg_kernel(const uint2* __restrict__ hsv, const int* __restrict__ off,
                const int* __restrict__ csr, const float* __restrict__ dinv,
                const float* __restrict__ bias, const int* __restrict__ batch,
                float4* __restrict__ outSum, float* __restrict__ gsum, int mode)
{
    int w = (blockIdx.x * blockDim.x + threadIdx.x) >> 5;
    if (w >= NN) return;
    int lane = threadIdx.x & 31;
    int o0 = __ldg(&off[w]);
    int o1 = __ldg(&off[w + 1]);

    float4 acc0 = make_float4(0.f, 0.f, 0.f, 0.f);
    float4 acc1 = make_float4(0.f, 0.f, 0.f, 0.f);
    acc_h4(acc0, __ldg(&hsv[(size_t)w * 32 + lane]));   // self-loop term

    int j = o0;
    for (; j + 4 <= o1; j += 4) {
        int s0 = __ldg(&csr[j]);
        int s1 = __ldg(&csr[j + 1]);
        int s2 = __ldg(&csr[j + 2]);
        int s3 = __ldg(&csr[j + 3]);
        uint2 v0 = __ldg(&hsv[(size_t)s0 * 32 + lane]);
        uint2 v1 = __ldg(&hsv[(size_t)s1 * 32 + lane]);
        uint2 v2 = __ldg(&hsv[(size_t)s2 * 32 + lane]);
        uint2 v3 = __ldg(&hsv[(size_t)s3 * 32 + lane]);
        acc_h4(acc0, v0); acc_h4(acc1, v1); acc_h4(acc0, v2); acc_h4(acc1, v3);
    }
    for (; j < o1; j++) {
        int s = __ldg(&csr[j]);
        acc_h4(acc0, __ldg(&hsv[(size_t)s * 32 + lane]));
    }
    acc0.x += acc1.x; acc0.y += acc1.y; acc0.z += acc1.z; acc0.w += acc1.w;

    if (mode == 0) {
        outSum[(size_t)w * 32 + lane] = acc0;
    } else {
        float di = __ldg(&dinv[w]);
        float4 bb = __ldg((const float4*)bias + lane);
        acc0.x = fmaxf(bb.x + di * acc0.x, 0.f);
        acc0.y = fmaxf(bb.y + di * acc0.y, 0.f);
        acc0.z = fmaxf(bb.z + di * acc0.z, 0.f);
        acc0.w = fmaxf(bb.w + di * acc0.w, 0.f);
        int b = __ldg(&batch[w]);
        red_add_v4(gsum + (size_t)b * 128 + lane * 4, acc0);
    }
}

// ---------------------------------------------------------------------------
// Fused head: 8 graphs per block, 128 threads (thread j owns output col j).
// ---------------------------------------------------------------------------
__global__ __launch_bounds__(128)
void final_kernel(const float* __restrict__ smiles,
                  const float* __restrict__ Ws1, const float* __restrict__ bs1,
                  const float* __restrict__ Ws2, const float* __restrict__ bs2,
                  const float* __restrict__ Wf,  const float* __restrict__ bf,
                  const float* __restrict__ Wo,  const float* __restrict__ bo,
                  const float* __restrict__ gsum, const int* __restrict__ cnt,
                  float* __restrict__ out) {
    __shared__ float sm[8][DS];
    __shared__ float s1[8][H];
    __shared__ float comb[8][2 * H];
    __shared__ float fz[8][H];

    const int b0 = blockIdx.x * 8;
    const int j = threadIdx.x;

    const float4* sp = (const float4*)(smiles + (size_t)b0 * DS);
#pragma unroll
    for (int i = 0; i < 12; i++)
        ((float4*)sm)[j + i * 128] = __ldg(sp + j + i * 128);
    __syncthreads();

    float a[8];
#pragma unroll
    for (int g = 0; g < 8; g++) a[g] = 0.f;
#pragma unroll 4
    for (int k = 0; k < DS; k++) {
        float w = __ldg(&Ws1[(size_t)k * H + j]);
#pragma unroll
        for (int g = 0; g < 8; g++) a[g] += sm[g][k] * w;
    }
    {
        float b1 = __ldg(&bs1[j]);
#pragma unroll
        for (int g = 0; g < 8; g++) s1[g][j] = fmaxf(a[g] + b1, 0.f);
    }
    __syncthreads();

#pragma unroll
    for (int g = 0; g < 8; g++) a[g] = 0.f;
#pragma unroll 4
    for (int k = 0; k < H; k++) {
        float w = __ldg(&Ws2[(size_t)k * H + j]);
#pragma unroll
        for (int g = 0; g < 8; g++) a[g] += s1[g][k] * w;
    }
    {
        float b2 = __ldg(&bs2[j]);
#pragma unroll
        for (int g = 0; g < 8; g++) {
            comb[g][j] = a[g] + b2;
            float c = (float)__ldg(&cnt[b0 + g]);
            comb[g][H + j] = __ldg(&gsum[(size_t)(b0 + g) * H + j]) / fmaxf(c, 1.f);
        }
    }
    __syncthreads();

#pragma unroll
    for (int g = 0; g < 8; g++) a[g] = 0.f;
#pragma unroll 4
    for (int k = 0; k < 2 * H; k++) {
        float w = __ldg(&Wf[(size_t)k * H + j]);
#pragma unroll
        for (int g = 0; g < 8; g++) a[g] += comb[g][k] * w;
    }
    {
        float bfv = __ldg(&bf[j]);
#pragma unroll
        for (int g = 0; g < 8; g++) fz[g][j] = fmaxf(a[g] + bfv, 0.f);
    }
    __syncthreads();

    if (j < 8 * NC) {
        int g = j / NC, c = j % NC;
        float s = __ldg(&bo[c]);
        for (int k = 0; k < H; k++)
            s += fz[g][k] * __ldg(&Wo[(size_t)k * NC + c]);
        out[(size_t)(b0 + g) * NC + c] = s;
    }
}

// ---------------------------------------------------------------------------
extern "C" void kernel_launch(void* const* d_in, const int* in_sizes, int n_in,
                              void* d_out, int out_size) {
    const float* smiles = (const float*)d_in[0];
    const float* x      = (const float*)d_in[1];
    const int*   ei     = (const int*)d_in[2];
    const int*   batch  = (const int*)d_in[3];
    const float* Ws1 = (const float*)d_in[4];
    const float* bs1 = (const float*)d_in[5];
    const float* Ws2 = (const float*)d_in[6];
    const float* bs2 = (const float*)d_in[7];
    const float* Wg1 = (const float*)d_in[8];
    const float* bg1 = (const float*)d_in[9];
    const float* Wg2 = (const float*)d_in[10];
    const float* bg2 = (const float*)d_in[11];
    const float* Wf  = (const float*)d_in[12];
    const float* bf  = (const float*)d_in[13];
    const float* Wo  = (const float*)d_in[14];
    const float* bo  = (const float*)d_in[15];
    float* out = (float*)d_out;

    float *bufB, *dinv, *gsum;
    __half *hsH;
    int *edeg, *off, *cursor, *csr, *blocksum, *blockoff, *cnt;
    cudaGetSymbolAddress((void**)&hsH,  g_hsH);
    cudaGetSymbolAddress((void**)&bufB, g_bufB);
    cudaGetSymbolAddress((void**)&dinv, g_dinv);
    cudaGetSymbolAddress((void**)&edeg, g_edeg);
    cudaGetSymbolAddress((void**)&off,  g_off);
    cudaGetSymbolAddress((void**)&cursor, g_cursor);
    cudaGetSymbolAddress((void**)&csr,  g_csr);
    cudaGetSymbolAddress((void**)&blocksum, g_blocksum);
    cudaGetSymbolAddress((void**)&blockoff, g_blockoff);
    cudaGetSymbolAddress((void**)&gsum, g_gsum);
    cudaGetSymbolAddress((void**)&cnt,  g_cnt);

    cudaFuncSetAttribute(gemm_tc_kernel,
                         cudaFuncAttributeMaxDynamicSharedMemorySize, GEMM_SMEM);

    const int* src = ei;
    const int* dst = ei + NE;

    const int T = 256;

    // --- preprocessing: degrees, counts, CSR by dst ---
    prep_zero_kernel<<<(NG * H + T - 1) / T, T>>>(edeg, cnt, gsum, off);
    count_kernel<<<(NE + T - 1) / T, T>>>(dst, batch, edeg, cnt);
    dinv_kernel<<<(NN + T - 1) / T, T>>>(edeg, dinv);
    scan1_kernel<<<SCAN_NB, SCAN_B>>>(edeg, blocksum);
    scan2_kernel<<<1, SCAN_B>>>(blocksum, blockoff);
    scan3_kernel<<<SCAN_NB, SCAN_B>>>(edeg, blockoff, off, cursor);
    scatter_kernel<<<(NE + T - 1) / T, T>>>(src, dst, cursor, csr);

    const int GEMM_GRID = 296;     // 2 per SM, persistent
    const int AGG_GRID  = (NN * 32 + T - 1) / T;

    // --- GCN layer 1 ---
    gemm_tc_kernel<<<GEMM_GRID, 256, GEMM_SMEM>>>(x, Wg1, dinv, bg1, hsH, NN, 0);
    agg_kernel<<<AGG_GRID, T>>>((const uint2*)hsH, off, csr, dinv, bg2, batch,
                                (float4*)bufB, gsum, 0);

    // --- GCN layer 2 (input transform relu(bg1 + dinv*sum1) inside GEMM) ---
    gemm_tc_kernel<<<GEMM_GRID, 256, GEMM_SMEM>>>(bufB, Wg2, dinv, bg1, hsH, NN, 1);
    // aggregate + fused pool into gsum
    agg_kernel<<<AGG_GRID, T>>>((const uint2*)hsH, off, csr, dinv, bg2, batch,
                                (float4*)bufB, gsum, 1);

    // --- SMILES MLP + fusion + output head ---
    final_kernel<<<NG / 8, 128>>>(smiles, Ws1, bs1, Ws2, bs2, Wf, bf, Wo, bo,
                                  gsum, cnt, out);
}